// round 3
// baseline (speedup 1.0000x reference)
#include <cuda_runtime.h>
#include <math.h>

// Problem constants
#define BB 32
#define JJ 512
#define EE 512
#define HH 8
#define MROWS (BB*JJ)          // 16384
#define EPSF 1e-7f
#define SP 516                 // S smem pitch in floats (516 mod 32 == 4)

// Scratch (device globals; no allocation allowed)
__device__ float g_qkv[MROWS * 3 * EE];   // [16384,1536]  q|k|v per row
__device__ float g_ztan[MROWS * EE];      // attn @ v, (B,J,E)
__device__ float g_ztan2[MROWS * EE];     // after out-proj

// ---------------------------------------------------------------------------
// TF32 helpers
// ---------------------------------------------------------------------------
__device__ __forceinline__ unsigned f2tf(float x) {
    unsigned u;
    asm("cvt.rna.tf32.f32 %0, %1;" : "=r"(u) : "f"(x));
    return u;
}

__device__ __forceinline__ void mma8(float (&c)[4], const unsigned (&a)[4],
                                     const unsigned (&b)[2]) {
    asm volatile(
        "mma.sync.aligned.m16n8k8.row.col.f32.tf32.tf32.f32 "
        "{%0,%1,%2,%3},{%4,%5,%6,%7},{%8,%9},{%0,%1,%2,%3};"
        : "+f"(c[0]), "+f"(c[1]), "+f"(c[2]), "+f"(c[3])
        : "r"(a[0]), "r"(a[1]), "r"(a[2]), "r"(a[3]), "r"(b[0]), "r"(b[1]));
}

// ---------------------------------------------------------------------------
// log_map0_spatial
// ---------------------------------------------------------------------------
__global__ void xtan_kernel(const float* __restrict__ x, float* __restrict__ xt) {
    int row = blockIdx.x;
    const float* p = x + (size_t)row * 513;
    float* o = xt + (size_t)row * 512;
    int t = threadIdx.x;  // 128 threads
    float v[4];
    float s = 0.f;
#pragma unroll
    for (int q = 0; q < 4; q++) { v[q] = p[1 + t + q * 128]; s += v[q] * v[q]; }
#pragma unroll
    for (int o2 = 16; o2 > 0; o2 >>= 1) s += __shfl_xor_sync(0xffffffffu, s, o2);
    __shared__ float sb[4];
    if ((t & 31) == 0) sb[t >> 5] = s;
    __syncthreads();
    float tot = sb[0] + sb[1] + sb[2] + sb[3];
    float nrm = sqrtf(tot);
    float x0 = fmaxf(p[0], 1.0f + 1e-7f);
    float theta = acoshf(x0);
    float sc = theta / fmaxf(nrm, EPSF);
#pragma unroll
    for (int q = 0; q < 4; q++) o[t + q * 128] = sc * v[q];
}

// ---------------------------------------------------------------------------
// exp_map0
// ---------------------------------------------------------------------------
__global__ void expmap_kernel(const float* __restrict__ zt, float* __restrict__ zm) {
    int row = blockIdx.x;
    const float* p = zt + (size_t)row * 512;
    float* o = zm + (size_t)row * 513;
    int t = threadIdx.x;
    float v[4];
    float s = 0.f;
#pragma unroll
    for (int q = 0; q < 4; q++) { v[q] = p[t + q * 128]; s += v[q] * v[q]; }
#pragma unroll
    for (int o2 = 16; o2 > 0; o2 >>= 1) s += __shfl_xor_sync(0xffffffffu, s, o2);
    __shared__ float sb[4];
    if ((t & 31) == 0) sb[t >> 5] = s;
    __syncthreads();
    float tot = sb[0] + sb[1] + sb[2] + sb[3];
    float nrm = sqrtf(tot);
    float sc = sinhf(nrm) / fmaxf(nrm, EPSF);
    if (t == 0) o[0] = coshf(nrm);
#pragma unroll
    for (int q = 0; q < 4; q++) o[1 + t + q * 128] = sc * v[q];
}

// ---------------------------------------------------------------------------
// Dense TC GEMM: C[M,N] (+)= A[M,K] * W[N,K]^T (+bias), TF32 mma
// BM=BN=128, BK=16, 256 threads = 8 warps (2x4), warp tile 64x32
// ---------------------------------------------------------------------------
__global__ void __launch_bounds__(256) gemm_nt_tc(
    const float* __restrict__ A, int lda, int a_aligned,
    const float* __restrict__ W, int ldb,
    float* __restrict__ C, int ldc, int K,
    const float* __restrict__ bias, int accflag) {
    __shared__ unsigned As[128][20];
    __shared__ unsigned Bs[128][20];
    int tid = threadIdx.x, lane = tid & 31, w = tid >> 5;
    int m0w = (w >> 2) * 64, n0w = (w & 3) * 32;
    const float* Ab = A + (size_t)blockIdx.y * 128 * lda;
    const float* Wb = W + (size_t)blockIdx.x * 128 * ldb;
    float c[4][4][4];
#pragma unroll
    for (int i = 0; i < 4; i++)
#pragma unroll
        for (int j = 0; j < 4; j++)
#pragma unroll
            for (int q = 0; q < 4; q++) c[i][j][q] = 0.f;

    for (int k0 = 0; k0 < K; k0 += 16) {
        if (a_aligned) {
#pragma unroll
            for (int q = 0; q < 2; q++) {
                int i = tid + q * 256;            // 0..511
                int r = i >> 2, c4 = (i & 3) * 4;
                float4 f = *(const float4*)(Ab + (size_t)r * lda + k0 + c4);
                uint4 u = make_uint4(f2tf(f.x), f2tf(f.y), f2tf(f.z), f2tf(f.w));
                *(uint4*)&As[r][c4] = u;
            }
        } else {
#pragma unroll
            for (int q = 0; q < 8; q++) {
                int i = tid + q * 256;            // 0..2047
                int r = i >> 4, cc = i & 15;
                As[r][cc] = f2tf(Ab[(size_t)r * lda + k0 + cc]);
            }
        }
#pragma unroll
        for (int q = 0; q < 2; q++) {
            int i = tid + q * 256;
            int r = i >> 2, c4 = (i & 3) * 4;
            float4 f = *(const float4*)(Wb + (size_t)r * ldb + k0 + c4);
            uint4 u = make_uint4(f2tf(f.x), f2tf(f.y), f2tf(f.z), f2tf(f.w));
            *(uint4*)&Bs[r][c4] = u;
        }
        __syncthreads();
#pragma unroll
        for (int ks = 0; ks < 16; ks += 8) {
            unsigned af[4][4], bf[4][2];
#pragma unroll
            for (int ma = 0; ma < 4; ma++) {
                int m = m0w + ma * 16 + (lane >> 2);
                int kk = ks + (lane & 3);
                af[ma][0] = As[m][kk];
                af[ma][1] = As[m + 8][kk];
                af[ma][2] = As[m][kk + 4];
                af[ma][3] = As[m + 8][kk + 4];
            }
#pragma unroll
            for (int nb = 0; nb < 4; nb++) {
                int n = n0w + nb * 8 + (lane >> 2);
                int kk = ks + (lane & 3);
                bf[nb][0] = Bs[n][kk];
                bf[nb][1] = Bs[n][kk + 4];
            }
#pragma unroll
            for (int ma = 0; ma < 4; ma++)
#pragma unroll
                for (int nb = 0; nb < 4; nb++) mma8(c[ma][nb], af[ma], bf[nb]);
        }
        __syncthreads();
    }
    int row0 = blockIdx.y * 128 + m0w;
    int col0 = blockIdx.x * 128 + n0w;
#pragma unroll
    for (int ma = 0; ma < 4; ma++)
#pragma unroll
        for (int nb = 0; nb < 4; nb++) {
            int r = row0 + ma * 16 + (lane >> 2);
            int cc = col0 + nb * 8 + 2 * (lane & 3);
            float2 v0 = make_float2(c[ma][nb][0], c[ma][nb][1]);
            float2 v1 = make_float2(c[ma][nb][2], c[ma][nb][3]);
            if (bias) {
                float bx = bias[cc], by = bias[cc + 1];
                v0.x += bx; v0.y += by; v1.x += bx; v1.y += by;
            }
            float* p0 = &C[(size_t)r * ldc + cc];
            float* p1 = &C[(size_t)(r + 8) * ldc + cc];
            if (accflag) {
                float2 o0 = *(float2*)p0, o1 = *(float2*)p1;
                v0.x += o0.x; v0.y += o0.y; v1.x += o1.x; v1.y += o1.y;
            }
            *(float2*)p0 = v0;
            *(float2*)p1 = v1;
        }
}

// ---------------------------------------------------------------------------
// Fused attention: per (q-tile 64, head) block.
//   stage 1: S = QK^T*scale + topo  -> smem strip [64][512] f32
//   stage 2: softmax rows in smem; write fp32 attn to gmem, tf32 bits to smem
//   stage 3: z = P @ V from smem    -> ztan (B,J,E)
// 256 threads = 8 warps laid out 4(m) x 2(n). grid (8, 256).
// Dynamic smem: S[64][516] f32 + Q[64][68] u32 + KV[64][68] u32 = 166912 B
// ---------------------------------------------------------------------------
extern "C" __global__ void __launch_bounds__(256) attn_fused(
    const float* __restrict__ qkv, const float* __restrict__ topo,
    float* __restrict__ attn, float* __restrict__ ztan) {
    extern __shared__ unsigned char smem_raw[];
    float* Ssm = (float*)smem_raw;                              // [64][SP]
    unsigned* Qs = (unsigned*)(smem_raw + (size_t)64 * SP * 4); // [64][68]
    unsigned* KVs = Qs + 64 * 68;                               // [64][68]

    int q0 = blockIdx.x * 64;
    int head = blockIdx.y;
    int b = head >> 3, h = head & 7;
    int tid = threadIdx.x, lane = tid & 31, w = tid >> 5;
    int wm = w >> 1, wn = w & 1;
    int m0 = wm * 16, n0w = wn * 32;
    const float* qbase = qkv + (size_t)b * 512 * 1536 + h * 64;
    const float* kbase = qbase + 512;
    const float* vbase = qbase + 1024;

    // ---- load Q tile (64x64) as tf32 ----
#pragma unroll
    for (int q = 0; q < 4; q++) {
        int i = tid + q * 256;                   // 0..1023
        int r = i >> 4, c4 = (i & 15) * 4;
        float4 f = *(const float4*)(qbase + (size_t)(q0 + r) * 1536 + c4);
        *(uint4*)&Qs[r * 68 + c4] = make_uint4(f2tf(f.x), f2tf(f.y), f2tf(f.z), f2tf(f.w));
    }

    // ---- stage 1: S strip ----
    for (int nc = 0; nc < 8; nc++) {
        __syncthreads();   // KVs reuse guard (also covers Q load on first iter)
#pragma unroll
        for (int q = 0; q < 4; q++) {
            int i = tid + q * 256;
            int r = i >> 4, c4 = (i & 15) * 4;
            float4 f = *(const float4*)(kbase + (size_t)(nc * 64 + r) * 1536 + c4);
            *(uint4*)&KVs[r * 68 + c4] = make_uint4(f2tf(f.x), f2tf(f.y), f2tf(f.z), f2tf(f.w));
        }
        __syncthreads();
        float c[4][4];
#pragma unroll
        for (int j = 0; j < 4; j++)
#pragma unroll
            for (int q = 0; q < 4; q++) c[j][q] = 0.f;
#pragma unroll
        for (int ks = 0; ks < 64; ks += 8) {
            int kk = ks + (lane & 3);
            int m = m0 + (lane >> 2);
            unsigned af[4];
            af[0] = Qs[m * 68 + kk];
            af[1] = Qs[(m + 8) * 68 + kk];
            af[2] = Qs[m * 68 + kk + 4];
            af[3] = Qs[(m + 8) * 68 + kk + 4];
            unsigned bf[4][2];
#pragma unroll
            for (int nb = 0; nb < 4; nb++) {
                int n = n0w + nb * 8 + (lane >> 2);
                bf[nb][0] = KVs[n * 68 + kk];
                bf[nb][1] = KVs[n * 68 + kk + 4];
            }
#pragma unroll
            for (int nb = 0; nb < 4; nb++) mma8(c[nb], af, bf[nb]);
        }
        const float scale = 0.125f;
        int mrow = m0 + (lane >> 2);
        int qi = q0 + mrow;
#pragma unroll
        for (int nb = 0; nb < 4; nb++) {
            int col = nc * 64 + n0w + nb * 8 + 2 * (lane & 3);
            float2 t0 = *(const float2*)&topo[(size_t)qi * 512 + col];
            float2 t1 = *(const float2*)&topo[(size_t)(qi + 8) * 512 + col];
            *(float2*)&Ssm[mrow * SP + col] =
                make_float2(c[nb][0] * scale + t0.x, c[nb][1] * scale + t0.y);
            *(float2*)&Ssm[(mrow + 8) * SP + col] =
                make_float2(c[nb][2] * scale + t1.x, c[nb][3] * scale + t1.y);
        }
    }
    __syncthreads();

    // ---- stage 2: softmax, warp w owns rows w*8 .. w*8+7 ----
    float* attn_base = attn + ((size_t)head * 512 + q0) * 512;
#pragma unroll
    for (int rr = 0; rr < 8; rr++) {
        int r = w * 8 + rr;
        float4 v[4];
        float mx = -1e30f;
#pragma unroll
        for (int q = 0; q < 4; q++) {
            v[q] = *(float4*)&Ssm[r * SP + (lane + q * 32) * 4];
            mx = fmaxf(mx, fmaxf(fmaxf(v[q].x, v[q].y), fmaxf(v[q].z, v[q].w)));
        }
#pragma unroll
        for (int o = 16; o > 0; o >>= 1) mx = fmaxf(mx, __shfl_xor_sync(0xffffffffu, mx, o));
        float s = 0.f;
#pragma unroll
        for (int q = 0; q < 4; q++) {
            v[q].x = expf(v[q].x - mx); v[q].y = expf(v[q].y - mx);
            v[q].z = expf(v[q].z - mx); v[q].w = expf(v[q].w - mx);
            s += v[q].x + v[q].y + v[q].z + v[q].w;
        }
#pragma unroll
        for (int o = 16; o > 0; o >>= 1) s += __shfl_xor_sync(0xffffffffu, s, o);
        float inv = 1.0f / s;
#pragma unroll
        for (int q = 0; q < 4; q++) {
            v[q].x *= inv; v[q].y *= inv; v[q].z *= inv; v[q].w *= inv;
            *(float4*)&attn_base[(size_t)r * 512 + (lane + q * 32) * 4] = v[q];
            *(uint4*)&Ssm[r * SP + (lane + q * 32) * 4] =
                make_uint4(f2tf(v[q].x), f2tf(v[q].y), f2tf(v[q].z), f2tf(v[q].w));
        }
    }

    // ---- stage 3: z = P @ V ----
    const unsigned* Pu = (const unsigned*)Ssm;
    float c2[4][4];
#pragma unroll
    for (int j = 0; j < 4; j++)
#pragma unroll
        for (int q = 0; q < 4; q++) c2[j][q] = 0.f;
    for (int kc = 0; kc < 8; kc++) {
        __syncthreads();
#pragma unroll
        for (int q = 0; q < 4; q++) {
            int i = tid + q * 256;
            int r = i >> 4, c4 = (i & 15) * 4;   // r = k-local, c4 = n
            float4 f = *(const float4*)(vbase + (size_t)(kc * 64 + r) * 1536 + c4);
            *(uint4*)&KVs[r * 68 + c4] = make_uint4(f2tf(f.x), f2tf(f.y), f2tf(f.z), f2tf(f.w));
        }
        __syncthreads();
#pragma unroll
        for (int ks = 0; ks < 64; ks += 8) {
            int kk = ks + (lane & 3);
            int m = m0 + (lane >> 2);
            int gk = kc * 64 + kk;
            unsigned af[4];
            af[0] = Pu[m * SP + gk];
            af[1] = Pu[(m + 8) * SP + gk];
            af[2] = Pu[m * SP + gk + 4];
            af[3] = Pu[(m + 8) * SP + gk + 4];
            unsigned bf[4][2];
#pragma unroll
            for (int nb = 0; nb < 4; nb++) {
                int n = n0w + nb * 8 + (lane >> 2);
                bf[nb][0] = KVs[kk * 68 + n];
                bf[nb][1] = KVs[(kk + 4) * 68 + n];
            }
#pragma unroll
            for (int nb = 0; nb < 4; nb++) mma8(c2[nb], af, bf[nb]);
        }
    }
#pragma unroll
    for (int nb = 0; nb < 4; nb++) {
        int row = b * 512 + q0 + m0 + (lane >> 2);
        int col = h * 64 + n0w + nb * 8 + 2 * (lane & 3);
        *(float2*)&ztan[(size_t)row * 512 + col] = make_float2(c2[nb][0], c2[nb][1]);
        *(float2*)&ztan[(size_t)(row + 8) * 512 + col] = make_float2(c2[nb][2], c2[nb][3]);
    }
}

// ---------------------------------------------------------------------------
extern "C" void kernel_launch(void* const* d_in, const int* in_sizes, int n_in,
                              void* d_out, int out_size) {
    const float* x       = (const float*)d_in[0];
    const float* x_vel   = (const float*)d_in[1];
    const float* topo    = (const float*)d_in[2];
    const float* W_qkv   = (const float*)d_in[3];
    const float* W_vproj = (const float*)d_in[4];
    const float* W_proj  = (const float*)d_in[5];
    const float* b_proj  = (const float*)d_in[6];

    float* out    = (float*)d_out;
    float* z_man  = out;                                   // 32*512*513
    float* attn   = out + (size_t)BB * JJ * (EE + 1);      // 32*8*512*512
    float* x_tan  = attn + (size_t)BB * HH * JJ * JJ;      // 32*512*512

    void *pq = nullptr, *pz = nullptr, *pz2 = nullptr;
    cudaGetSymbolAddress(&pq, g_qkv);
    cudaGetSymbolAddress(&pz, g_ztan);
    cudaGetSymbolAddress(&pz2, g_ztan2);
    float* qkv   = (float*)pq;
    float* ztan  = (float*)pz;
    float* ztan2 = (float*)pz2;

    const int fused_smem = (64 * SP + 2 * 64 * 68) * 4;    // 166912 B
    cudaFuncSetAttribute(attn_fused, cudaFuncAttributeMaxDynamicSharedMemorySize,
                         fused_smem);

    // 1. log-map -> x_tan (also an output)
    xtan_kernel<<<MROWS, 128>>>(x, x_tan);

    // 2. qkv = x_tan @ W_qkv^T   (M=16384, N=1536, K=512)
    {
        dim3 g(1536 / 128, MROWS / 128);
        gemm_nt_tc<<<g, 256>>>(x_tan, 512, 1, W_qkv, 512, qkv, 1536, 512, nullptr, 0);
    }
    // 3. k += v_tan @ W_vproj^T  (accumulate into k slab; unaligned A)
    {
        dim3 g(512 / 128, MROWS / 128);
        gemm_nt_tc<<<g, 256>>>(x_vel + 1, 513, 0, W_vproj, 512, qkv + 512, 1536, 512,
                               nullptr, 1);
    }
    // 4-6. fused S + softmax + PV
    {
        dim3 g(8, BB * HH);
        attn_fused<<<g, 256, fused_smem>>>(qkv, topo, attn, ztan);
    }
    // 7. out-proj: ztan2 = ztan @ W_proj^T + b_proj
    {
        dim3 g(512 / 128, MROWS / 128);
        gemm_nt_tc<<<g, 256>>>(ztan, 512, 1, W_proj, 512, ztan2, 512, 512, b_proj, 0);
    }
    // 8. exp-map -> z_manifold
    expmap_kernel<<<MROWS, 128>>>(ztan2, z_man);
}

// round 4
// speedup vs baseline: 1.7547x; 1.7547x over previous
#include <cuda_runtime.h>
#include <cuda_bf16.h>
#include <math.h>

// Problem constants
#define BB 32
#define JJ 512
#define EE 512
#define HH 8
#define MROWS (BB*JJ)          // 16384
#define EPSF 1e-7f

// Scratch (device globals; no allocation allowed)
__device__ float g_qkv[MROWS * 3 * EE];   // [16384,1536]  q|k|v per row
__device__ float g_ztan[MROWS * EE];      // attn @ v, (B,J,E)
__device__ float g_ztan2[MROWS * EE];     // after out-proj

// ---------------------------------------------------------------------------
// bf16 helpers
// ---------------------------------------------------------------------------
__device__ __forceinline__ unsigned pk2(float lo, float hi) {
    __nv_bfloat162 t = __floats2bfloat162_rn(lo, hi);
    return *reinterpret_cast<unsigned*>(&t);
}

__device__ __forceinline__ void mma16(float (&c)[4], const unsigned (&a)[4],
                                      const unsigned (&b)[2]) {
    asm volatile(
        "mma.sync.aligned.m16n8k16.row.col.f32.bf16.bf16.f32 "
        "{%0,%1,%2,%3},{%4,%5,%6,%7},{%8,%9},{%0,%1,%2,%3};"
        : "+f"(c[0]), "+f"(c[1]), "+f"(c[2]), "+f"(c[3])
        : "r"(a[0]), "r"(a[1]), "r"(a[2]), "r"(a[3]), "r"(b[0]), "r"(b[1]));
}

// ---------------------------------------------------------------------------
// log_map0_spatial
// ---------------------------------------------------------------------------
__global__ void xtan_kernel(const float* __restrict__ x, float* __restrict__ xt) {
    int row = blockIdx.x;
    const float* p = x + (size_t)row * 513;
    float* o = xt + (size_t)row * 512;
    int t = threadIdx.x;  // 128 threads
    float v[4];
    float s = 0.f;
#pragma unroll
    for (int q = 0; q < 4; q++) { v[q] = p[1 + t + q * 128]; s += v[q] * v[q]; }
#pragma unroll
    for (int o2 = 16; o2 > 0; o2 >>= 1) s += __shfl_xor_sync(0xffffffffu, s, o2);
    __shared__ float sb[4];
    if ((t & 31) == 0) sb[t >> 5] = s;
    __syncthreads();
    float tot = sb[0] + sb[1] + sb[2] + sb[3];
    float nrm = sqrtf(tot);
    float x0 = fmaxf(p[0], 1.0f + 1e-7f);
    float theta = acoshf(x0);
    float sc = theta / fmaxf(nrm, EPSF);
#pragma unroll
    for (int q = 0; q < 4; q++) o[t + q * 128] = sc * v[q];
}

// ---------------------------------------------------------------------------
// exp_map0
// ---------------------------------------------------------------------------
__global__ void expmap_kernel(const float* __restrict__ zt, float* __restrict__ zm) {
    int row = blockIdx.x;
    const float* p = zt + (size_t)row * 512;
    float* o = zm + (size_t)row * 513;
    int t = threadIdx.x;
    float v[4];
    float s = 0.f;
#pragma unroll
    for (int q = 0; q < 4; q++) { v[q] = p[t + q * 128]; s += v[q] * v[q]; }
#pragma unroll
    for (int o2 = 16; o2 > 0; o2 >>= 1) s += __shfl_xor_sync(0xffffffffu, s, o2);
    __shared__ float sb[4];
    if ((t & 31) == 0) sb[t >> 5] = s;
    __syncthreads();
    float tot = sb[0] + sb[1] + sb[2] + sb[3];
    float nrm = sqrtf(tot);
    float sc = sinhf(nrm) / fmaxf(nrm, EPSF);
    if (t == 0) o[0] = coshf(nrm);
#pragma unroll
    for (int q = 0; q < 4; q++) o[1 + t + q * 128] = sc * v[q];
}

// ---------------------------------------------------------------------------
// Dense TC GEMM (bf16): C[M,N] (+)= A[M,K] * W[N,K]^T (+bias)
// BM=BN=128, BK=32, 256 threads = 8 warps (2x4), warp tile 64x32.
// smem pitch 20 words (40 halves) -> conflict-free fragment LDS.
// ---------------------------------------------------------------------------
__global__ void __launch_bounds__(256) gemm_nt_bf(
    const float* __restrict__ A, int lda, int a_aligned,
    const float* __restrict__ W, int ldb,
    float* __restrict__ C, int ldc, int K,
    const float* __restrict__ bias, int accflag) {
    __shared__ unsigned As[128 * 20];
    __shared__ unsigned Bs[128 * 20];
    int tid = threadIdx.x, lane = tid & 31, w = tid >> 5;
    int gr = lane >> 2, lq = lane & 3;
    int m0w = (w >> 2) * 64, n0w = (w & 3) * 32;
    const float* Ab = A + (size_t)blockIdx.y * 128 * lda;
    const float* Wb = W + (size_t)blockIdx.x * 128 * ldb;
    float c[4][4][4];
#pragma unroll
    for (int i = 0; i < 4; i++)
#pragma unroll
        for (int j = 0; j < 4; j++)
#pragma unroll
            for (int q = 0; q < 4; q++) c[i][j][q] = 0.f;

    for (int k0 = 0; k0 < K; k0 += 32) {
        if (a_aligned) {
#pragma unroll
            for (int q = 0; q < 4; q++) {
                int i = tid + q * 256;            // 0..1023
                int r = i >> 3, c4 = (i & 7) * 4;
                float4 f = *(const float4*)(Ab + (size_t)r * lda + k0 + c4);
                *(uint2*)&As[r * 20 + c4 / 2] = make_uint2(pk2(f.x, f.y), pk2(f.z, f.w));
            }
        } else {
#pragma unroll
            for (int q = 0; q < 16; q++) {
                int i = tid + q * 256;            // 0..4095
                int r = i >> 5, cc = i & 31;
                ((__nv_bfloat16*)As)[r * 40 + cc] =
                    __float2bfloat16(Ab[(size_t)r * lda + k0 + cc]);
            }
        }
#pragma unroll
        for (int q = 0; q < 4; q++) {
            int i = tid + q * 256;
            int r = i >> 3, c4 = (i & 7) * 4;
            float4 f = *(const float4*)(Wb + (size_t)r * ldb + k0 + c4);
            *(uint2*)&Bs[r * 20 + c4 / 2] = make_uint2(pk2(f.x, f.y), pk2(f.z, f.w));
        }
        __syncthreads();
#pragma unroll
        for (int ks = 0; ks < 32; ks += 16) {
            int kw = ks >> 1;
            unsigned af[4][4], bf[4][2];
#pragma unroll
            for (int ma = 0; ma < 4; ma++) {
                int m = m0w + ma * 16 + gr;
                af[ma][0] = As[m * 20 + kw + lq];
                af[ma][1] = As[(m + 8) * 20 + kw + lq];
                af[ma][2] = As[m * 20 + kw + 4 + lq];
                af[ma][3] = As[(m + 8) * 20 + kw + 4 + lq];
            }
#pragma unroll
            for (int nb = 0; nb < 4; nb++) {
                int n = n0w + nb * 8 + gr;
                bf[nb][0] = Bs[n * 20 + kw + lq];
                bf[nb][1] = Bs[n * 20 + kw + 4 + lq];
            }
#pragma unroll
            for (int ma = 0; ma < 4; ma++)
#pragma unroll
                for (int nb = 0; nb < 4; nb++) mma16(c[ma][nb], af[ma], bf[nb]);
        }
        __syncthreads();
    }
    int row0 = blockIdx.y * 128 + m0w;
    int col0 = blockIdx.x * 128 + n0w;
#pragma unroll
    for (int ma = 0; ma < 4; ma++)
#pragma unroll
        for (int nb = 0; nb < 4; nb++) {
            int r = row0 + ma * 16 + gr;
            int cc = col0 + nb * 8 + 2 * lq;
            float2 v0 = make_float2(c[ma][nb][0], c[ma][nb][1]);
            float2 v1 = make_float2(c[ma][nb][2], c[ma][nb][3]);
            if (bias) {
                float bx = bias[cc], by = bias[cc + 1];
                v0.x += bx; v0.y += by; v1.x += bx; v1.y += by;
            }
            float* p0 = &C[(size_t)r * ldc + cc];
            float* p1 = &C[(size_t)(r + 8) * ldc + cc];
            if (accflag) {
                float2 o0 = *(float2*)p0, o1 = *(float2*)p1;
                v0.x += o0.x; v0.y += o0.y; v1.x += o1.x; v1.y += o1.y;
            }
            *(float2*)p0 = v0;
            *(float2*)p1 = v1;
        }
}

// ---------------------------------------------------------------------------
// Fused attention v2 (chunked, occupancy-preserving).
// Block = (64 q-rows, head). 256 threads = 8 warps, 4(m) x 2(n), warp tile 16x32.
// Pass A: S chunks (recompute), exact online row max/sum.
// Pass B: recompute S chunk, normalize, write attn once, P@V from smem.
// Static smem ~38.4 KB -> ~3 CTAs/SM.
// ---------------------------------------------------------------------------
__global__ void __launch_bounds__(256) attn_fused2(
    const float* __restrict__ qkv, const float* __restrict__ topo,
    float* __restrict__ attn, float* __restrict__ ztan) {
    __shared__ unsigned Qs[64 * 36];   // [row][k/2] words, pitch 36 (mod 32 == 4)
    __shared__ unsigned Ks[64 * 36];   // [key][k/2] words
    __shared__ unsigned Vs[32 * 72];   // [k/2][n] pair-packed words, pitch 72 (mod 32 == 8)
    __shared__ unsigned Ps[64 * 36];   // [row][col/2] words
    __shared__ float rm[64], rs[64];
    __shared__ float pmax[64][2], psum[64][2];

    int q0 = blockIdx.x * 64;
    int head = blockIdx.y;
    int b = head >> 3, h = head & 7;
    int tid = threadIdx.x, lane = tid & 31, w = tid >> 5;
    int wm = w >> 1, wn = w & 1;
    int m0 = wm * 16, n0 = wn * 32;
    int gr = lane >> 2, lq = lane & 3;
    const float* qbase = qkv + (size_t)b * 512 * 1536 + h * 64;
    const float* kbase = qbase + 512;
    const float* vbase = qbase + 1024;

    if (tid < 64) { rm[tid] = -1e30f; rs[tid] = 0.f; }
    // Q tile 64x64 -> bf16
#pragma unroll
    for (int q = 0; q < 4; q++) {
        int i = tid + q * 256;
        int r = i >> 4, c4 = (i & 15) * 4;
        float4 f = *(const float4*)(qbase + (size_t)(q0 + r) * 1536 + c4);
        *(uint2*)&Qs[r * 36 + c4 / 2] = make_uint2(pk2(f.x, f.y), pk2(f.z, f.w));
    }
    int r0 = m0 + gr, r1 = r0 + 8;
    int qi = q0 + r0;
    const float scale = 0.125f;

    // ---------------- Pass A: row max & sum ----------------
    for (int nc = 0; nc < 8; nc++) {
        __syncthreads();
#pragma unroll
        for (int q = 0; q < 4; q++) {
            int i = tid + q * 256;
            int r = i >> 4, c4 = (i & 15) * 4;
            float4 f = *(const float4*)(kbase + (size_t)(nc * 64 + r) * 1536 + c4);
            *(uint2*)&Ks[r * 36 + c4 / 2] = make_uint2(pk2(f.x, f.y), pk2(f.z, f.w));
        }
        __syncthreads();
        float c[4][4];
#pragma unroll
        for (int j = 0; j < 4; j++)
#pragma unroll
            for (int q = 0; q < 4; q++) c[j][q] = 0.f;
#pragma unroll
        for (int ks = 0; ks < 64; ks += 16) {
            int kw = ks >> 1;
            unsigned a[4];
            a[0] = Qs[r0 * 36 + kw + lq];
            a[1] = Qs[r1 * 36 + kw + lq];
            a[2] = Qs[r0 * 36 + kw + 4 + lq];
            a[3] = Qs[r1 * 36 + kw + 4 + lq];
#pragma unroll
            for (int nb = 0; nb < 4; nb++) {
                int n = n0 + nb * 8 + gr;
                unsigned bb[2];
                bb[0] = Ks[n * 36 + kw + lq];
                bb[1] = Ks[n * 36 + kw + 4 + lq];
                mma16(c[nb], a, bb);
            }
        }
        float v[4][4];
        float tm0 = -1e30f, tm1 = -1e30f;
#pragma unroll
        for (int nb = 0; nb < 4; nb++) {
            int gc = nc * 64 + n0 + nb * 8 + 2 * lq;
            float2 t0 = *(const float2*)&topo[(size_t)qi * 512 + gc];
            float2 t1 = *(const float2*)&topo[(size_t)(qi + 8) * 512 + gc];
            v[nb][0] = c[nb][0] * scale + t0.x;
            v[nb][1] = c[nb][1] * scale + t0.y;
            v[nb][2] = c[nb][2] * scale + t1.x;
            v[nb][3] = c[nb][3] * scale + t1.y;
            tm0 = fmaxf(tm0, fmaxf(v[nb][0], v[nb][1]));
            tm1 = fmaxf(tm1, fmaxf(v[nb][2], v[nb][3]));
        }
        tm0 = fmaxf(tm0, __shfl_xor_sync(0xffffffffu, tm0, 1));
        tm0 = fmaxf(tm0, __shfl_xor_sync(0xffffffffu, tm0, 2));
        tm1 = fmaxf(tm1, __shfl_xor_sync(0xffffffffu, tm1, 1));
        tm1 = fmaxf(tm1, __shfl_xor_sync(0xffffffffu, tm1, 2));
        if (lq == 0) { pmax[r0][wn] = tm0; pmax[r1][wn] = tm1; }
        __syncthreads();
        float old0 = rm[r0], old1 = rm[r1];
        float nm0 = fmaxf(old0, fmaxf(pmax[r0][0], pmax[r0][1]));
        float nm1 = fmaxf(old1, fmaxf(pmax[r1][0], pmax[r1][1]));
        float s0 = 0.f, s1 = 0.f;
#pragma unroll
        for (int nb = 0; nb < 4; nb++) {
            s0 += __expf(v[nb][0] - nm0) + __expf(v[nb][1] - nm0);
            s1 += __expf(v[nb][2] - nm1) + __expf(v[nb][3] - nm1);
        }
        s0 += __shfl_xor_sync(0xffffffffu, s0, 1);
        s0 += __shfl_xor_sync(0xffffffffu, s0, 2);
        s1 += __shfl_xor_sync(0xffffffffu, s1, 1);
        s1 += __shfl_xor_sync(0xffffffffu, s1, 2);
        if (lq == 0) { psum[r0][wn] = s0; psum[r1][wn] = s1; }
        __syncthreads();
        if (wn == 0 && lq == 0) {
            rs[r0] = rs[r0] * __expf(old0 - nm0) + psum[r0][0] + psum[r0][1];
            rm[r0] = nm0;
            rs[r1] = rs[r1] * __expf(old1 - nm1) + psum[r1][0] + psum[r1][1];
            rm[r1] = nm1;
        }
    }
    __syncthreads();
    if (tid < 64) rs[tid] = 1.0f / rs[tid];

    // ---------------- Pass B: normalize + write attn + P@V ----------------
    float z[4][4];
#pragma unroll
    for (int j = 0; j < 4; j++)
#pragma unroll
        for (int q = 0; q < 4; q++) z[j][q] = 0.f;
    float* attn_base = attn + ((size_t)head * 512 + q0) * 512;

    for (int kc = 0; kc < 8; kc++) {
        __syncthreads();
#pragma unroll
        for (int q = 0; q < 4; q++) {
            int i = tid + q * 256;
            int r = i >> 4, c4 = (i & 15) * 4;
            float4 f = *(const float4*)(kbase + (size_t)(kc * 64 + r) * 1536 + c4);
            *(uint2*)&Ks[r * 36 + c4 / 2] = make_uint2(pk2(f.x, f.y), pk2(f.z, f.w));
        }
#pragma unroll
        for (int q = 0; q < 4; q++) {
            int i = tid + q * 256;                 // 0..1023
            int kp = i >> 5, n2 = (i & 31) * 2;
            const float* vr = vbase + (size_t)(kc * 64 + 2 * kp) * 1536 + n2;
            float2 f0 = *(const float2*)vr;
            float2 f1 = *(const float2*)(vr + 1536);
            *(uint2*)&Vs[kp * 72 + n2] = make_uint2(pk2(f0.x, f1.x), pk2(f0.y, f1.y));
        }
        __syncthreads();
        // recompute S chunk
        float c[4][4];
#pragma unroll
        for (int j = 0; j < 4; j++)
#pragma unroll
            for (int q = 0; q < 4; q++) c[j][q] = 0.f;
#pragma unroll
        for (int ks = 0; ks < 64; ks += 16) {
            int kw = ks >> 1;
            unsigned a[4];
            a[0] = Qs[r0 * 36 + kw + lq];
            a[1] = Qs[r1 * 36 + kw + lq];
            a[2] = Qs[r0 * 36 + kw + 4 + lq];
            a[3] = Qs[r1 * 36 + kw + 4 + lq];
#pragma unroll
            for (int nb = 0; nb < 4; nb++) {
                int n = n0 + nb * 8 + gr;
                unsigned bb[2];
                bb[0] = Ks[n * 36 + kw + lq];
                bb[1] = Ks[n * 36 + kw + 4 + lq];
                mma16(c[nb], a, bb);
            }
        }
        float m_0 = rm[r0], m_1 = rm[r1];
        float i_0 = rs[r0], i_1 = rs[r1];
#pragma unroll
        for (int nb = 0; nb < 4; nb++) {
            int cc = n0 + nb * 8 + 2 * lq;
            int gc = kc * 64 + cc;
            float2 t0 = *(const float2*)&topo[(size_t)qi * 512 + gc];
            float2 t1 = *(const float2*)&topo[(size_t)(qi + 8) * 512 + gc];
            float p00 = __expf(c[nb][0] * scale + t0.x - m_0) * i_0;
            float p01 = __expf(c[nb][1] * scale + t0.y - m_0) * i_0;
            float p10 = __expf(c[nb][2] * scale + t1.x - m_1) * i_1;
            float p11 = __expf(c[nb][3] * scale + t1.y - m_1) * i_1;
            *(float2*)&attn_base[(size_t)r0 * 512 + gc] = make_float2(p00, p01);
            *(float2*)&attn_base[(size_t)r1 * 512 + gc] = make_float2(p10, p11);
            Ps[r0 * 36 + cc / 2] = pk2(p00, p01);
            Ps[r1 * 36 + cc / 2] = pk2(p10, p11);
        }
        __syncthreads();
        // z += P @ V
#pragma unroll
        for (int ks = 0; ks < 64; ks += 16) {
            int kw = ks >> 1;
            unsigned a[4];
            a[0] = Ps[r0 * 36 + kw + lq];
            a[1] = Ps[r1 * 36 + kw + lq];
            a[2] = Ps[r0 * 36 + kw + 4 + lq];
            a[3] = Ps[r1 * 36 + kw + 4 + lq];
#pragma unroll
            for (int nb = 0; nb < 4; nb++) {
                int n = n0 + nb * 8 + gr;
                unsigned bb[2];
                bb[0] = Vs[(kw + lq) * 72 + n];
                bb[1] = Vs[(kw + lq + 4) * 72 + n];
                mma16(z[nb], a, bb);
            }
        }
    }
    // epilogue -> ztan (B,J,E)
    int orow = b * 512 + q0 + r0;
#pragma unroll
    for (int nb = 0; nb < 4; nb++) {
        int col = h * 64 + n0 + nb * 8 + 2 * lq;
        *(float2*)&ztan[(size_t)orow * 512 + col] = make_float2(z[nb][0], z[nb][1]);
        *(float2*)&ztan[(size_t)(orow + 8) * 512 + col] = make_float2(z[nb][2], z[nb][3]);
    }
}

// ---------------------------------------------------------------------------
extern "C" void kernel_launch(void* const* d_in, const int* in_sizes, int n_in,
                              void* d_out, int out_size) {
    const float* x       = (const float*)d_in[0];
    const float* x_vel   = (const float*)d_in[1];
    const float* topo    = (const float*)d_in[2];
    const float* W_qkv   = (const float*)d_in[3];
    const float* W_vproj = (const float*)d_in[4];
    const float* W_proj  = (const float*)d_in[5];
    const float* b_proj  = (const float*)d_in[6];

    float* out    = (float*)d_out;
    float* z_man  = out;                                   // 32*512*513
    float* attn   = out + (size_t)BB * JJ * (EE + 1);      // 32*8*512*512
    float* x_tan  = attn + (size_t)BB * HH * JJ * JJ;      // 32*512*512

    void *pq = nullptr, *pz = nullptr, *pz2 = nullptr;
    cudaGetSymbolAddress(&pq, g_qkv);
    cudaGetSymbolAddress(&pz, g_ztan);
    cudaGetSymbolAddress(&pz2, g_ztan2);
    float* qkv   = (float*)pq;
    float* ztan  = (float*)pz;
    float* ztan2 = (float*)pz2;

    // 1. log-map -> x_tan (also an output)
    xtan_kernel<<<MROWS, 128>>>(x, x_tan);

    // 2. qkv = x_tan @ W_qkv^T   (M=16384, N=1536, K=512)
    {
        dim3 g(1536 / 128, MROWS / 128);
        gemm_nt_bf<<<g, 256>>>(x_tan, 512, 1, W_qkv, 512, qkv, 1536, 512, nullptr, 0);
    }
    // 3. k += v_tan @ W_vproj^T  (accumulate into k slab; unaligned A)
    {
        dim3 g(512 / 128, MROWS / 128);
        gemm_nt_bf<<<g, 256>>>(x_vel + 1, 513, 0, W_vproj, 512, qkv + 512, 1536, 512,
                               nullptr, 1);
    }
    // 4-6. fused S + softmax + PV (chunked)
    {
        dim3 g(8, BB * HH);
        attn_fused2<<<g, 256>>>(qkv, topo, attn, ztan);
    }
    // 7. out-proj: ztan2 = ztan @ W_proj^T + b_proj
    {
        dim3 g(512 / 128, MROWS / 128);
        gemm_nt_bf<<<g, 256>>>(ztan, 512, 1, W_proj, 512, ztan2, 512, 512, b_proj, 0);
    }
    // 8. exp-map -> z_manifold
    expmap_kernel<<<MROWS, 128>>>(ztan2, z_man);
}

// round 5
// speedup vs baseline: 2.3573x; 1.3434x over previous
#include <cuda_runtime.h>
#include <cuda_bf16.h>
#include <math.h>

// Problem constants
#define BB 32
#define JJ 512
#define EE 512
#define HH 8
#define MROWS (BB*JJ)          // 16384
#define EPSF 1e-7f

// Scratch (device globals; no allocation allowed)
__device__ float g_qkv[MROWS * 3 * EE];   // [16384,1536]  q|k|v per row
__device__ float g_ztan[MROWS * EE];      // attn @ v, (B,J,E)
__device__ float g_ztan2[MROWS * EE];     // out-proj result; also vel staging early

// ---------------------------------------------------------------------------
// bf16 helpers
// ---------------------------------------------------------------------------
__device__ __forceinline__ unsigned pk2(float lo, float hi) {
    __nv_bfloat162 t = __floats2bfloat162_rn(lo, hi);
    return *reinterpret_cast<unsigned*>(&t);
}

__device__ __forceinline__ void mma16(float (&c)[4], const unsigned (&a)[4],
                                      const unsigned (&b)[2]) {
    asm volatile(
        "mma.sync.aligned.m16n8k16.row.col.f32.bf16.bf16.f32 "
        "{%0,%1,%2,%3},{%4,%5,%6,%7},{%8,%9},{%0,%1,%2,%3};"
        : "+f"(c[0]), "+f"(c[1]), "+f"(c[2]), "+f"(c[3])
        : "r"(a[0]), "r"(a[1]), "r"(a[2]), "r"(a[3]), "r"(b[0]), "r"(b[1]));
}

// ---------------------------------------------------------------------------
// log_map0_spatial
// ---------------------------------------------------------------------------
__global__ void xtan_kernel(const float* __restrict__ x, float* __restrict__ xt) {
    int row = blockIdx.x;
    const float* p = x + (size_t)row * 513;
    float* o = xt + (size_t)row * 512;
    int t = threadIdx.x;  // 128 threads
    float v[4];
    float s = 0.f;
#pragma unroll
    for (int q = 0; q < 4; q++) { v[q] = p[1 + t + q * 128]; s += v[q] * v[q]; }
#pragma unroll
    for (int o2 = 16; o2 > 0; o2 >>= 1) s += __shfl_xor_sync(0xffffffffu, s, o2);
    __shared__ float sb[4];
    if ((t & 31) == 0) sb[t >> 5] = s;
    __syncthreads();
    float tot = sb[0] + sb[1] + sb[2] + sb[3];
    float nrm = sqrtf(tot);
    float x0 = fmaxf(p[0], 1.0f + 1e-7f);
    float theta = acoshf(x0);
    float sc = theta / fmaxf(nrm, EPSF);
#pragma unroll
    for (int q = 0; q < 4; q++) o[t + q * 128] = sc * v[q];
}

// ---------------------------------------------------------------------------
// stage x_vel[...,1:] into aligned [rows,512] buffer
// ---------------------------------------------------------------------------
__global__ void vel_copy_kernel(const float* __restrict__ xv, float* __restrict__ o) {
    int row = blockIdx.x;
    const float* p = xv + (size_t)row * 513 + 1;
    float* q = o + (size_t)row * 512;
    int t = threadIdx.x;  // 128
#pragma unroll
    for (int i = 0; i < 4; i++) q[t + i * 128] = p[t + i * 128];
}

// ---------------------------------------------------------------------------
// exp_map0
// ---------------------------------------------------------------------------
__global__ void expmap_kernel(const float* __restrict__ zt, float* __restrict__ zm) {
    int row = blockIdx.x;
    const float* p = zt + (size_t)row * 512;
    float* o = zm + (size_t)row * 513;
    int t = threadIdx.x;
    float v[4];
    float s = 0.f;
#pragma unroll
    for (int q = 0; q < 4; q++) { v[q] = p[t + q * 128]; s += v[q] * v[q]; }
#pragma unroll
    for (int o2 = 16; o2 > 0; o2 >>= 1) s += __shfl_xor_sync(0xffffffffu, s, o2);
    __shared__ float sb[4];
    if ((t & 31) == 0) sb[t >> 5] = s;
    __syncthreads();
    float tot = sb[0] + sb[1] + sb[2] + sb[3];
    float nrm = sqrtf(tot);
    float sc = sinhf(nrm) / fmaxf(nrm, EPSF);
    if (t == 0) o[0] = coshf(nrm);
#pragma unroll
    for (int q = 0; q < 4; q++) o[1 + t + q * 128] = sc * v[q];
}

// ---------------------------------------------------------------------------
// Dense TC GEMM (bf16): C[M,N] (+)= A[M,K] * W[N,K]^T (+bias)
// BM=BN=128, BK=32, 256 threads = 8 warps (2x4), warp tile 64x32.
// ---------------------------------------------------------------------------
__global__ void __launch_bounds__(256) gemm_nt_bf(
    const float* __restrict__ A, int lda,
    const float* __restrict__ W, int ldb,
    float* __restrict__ C, int ldc, int K,
    const float* __restrict__ bias, int accflag) {
    __shared__ unsigned As[128 * 20];
    __shared__ unsigned Bs[128 * 20];
    int tid = threadIdx.x, lane = tid & 31, w = tid >> 5;
    int gr = lane >> 2, lq = lane & 3;
    int m0w = (w >> 2) * 64, n0w = (w & 3) * 32;
    const float* Ab = A + (size_t)blockIdx.y * 128 * lda;
    const float* Wb = W + (size_t)blockIdx.x * 128 * ldb;
    float c[4][4][4];
#pragma unroll
    for (int i = 0; i < 4; i++)
#pragma unroll
        for (int j = 0; j < 4; j++)
#pragma unroll
            for (int q = 0; q < 4; q++) c[i][j][q] = 0.f;

    for (int k0 = 0; k0 < K; k0 += 32) {
#pragma unroll
        for (int q = 0; q < 4; q++) {
            int i = tid + q * 256;            // 0..1023
            int r = i >> 3, c4 = (i & 7) * 4;
            float4 f = *(const float4*)(Ab + (size_t)r * lda + k0 + c4);
            *(uint2*)&As[r * 20 + c4 / 2] = make_uint2(pk2(f.x, f.y), pk2(f.z, f.w));
        }
#pragma unroll
        for (int q = 0; q < 4; q++) {
            int i = tid + q * 256;
            int r = i >> 3, c4 = (i & 7) * 4;
            float4 f = *(const float4*)(Wb + (size_t)r * ldb + k0 + c4);
            *(uint2*)&Bs[r * 20 + c4 / 2] = make_uint2(pk2(f.x, f.y), pk2(f.z, f.w));
        }
        __syncthreads();
#pragma unroll
        for (int ks = 0; ks < 32; ks += 16) {
            int kw = ks >> 1;
            unsigned af[4][4], bf[4][2];
#pragma unroll
            for (int ma = 0; ma < 4; ma++) {
                int m = m0w + ma * 16 + gr;
                af[ma][0] = As[m * 20 + kw + lq];
                af[ma][1] = As[(m + 8) * 20 + kw + lq];
                af[ma][2] = As[m * 20 + kw + 4 + lq];
                af[ma][3] = As[(m + 8) * 20 + kw + 4 + lq];
            }
#pragma unroll
            for (int nb = 0; nb < 4; nb++) {
                int n = n0w + nb * 8 + gr;
                bf[nb][0] = Bs[n * 20 + kw + lq];
                bf[nb][1] = Bs[n * 20 + kw + 4 + lq];
            }
#pragma unroll
            for (int ma = 0; ma < 4; ma++)
#pragma unroll
                for (int nb = 0; nb < 4; nb++) mma16(c[ma][nb], af[ma], bf[nb]);
        }
        __syncthreads();
    }
    int row0 = blockIdx.y * 128 + m0w;
    int col0 = blockIdx.x * 128 + n0w;
#pragma unroll
    for (int ma = 0; ma < 4; ma++)
#pragma unroll
        for (int nb = 0; nb < 4; nb++) {
            int r = row0 + ma * 16 + gr;
            int cc = col0 + nb * 8 + 2 * lq;
            float2 v0 = make_float2(c[ma][nb][0], c[ma][nb][1]);
            float2 v1 = make_float2(c[ma][nb][2], c[ma][nb][3]);
            if (bias) {
                float bx = bias[cc], by = bias[cc + 1];
                v0.x += bx; v0.y += by; v1.x += bx; v1.y += by;
            }
            float* p0 = &C[(size_t)r * ldc + cc];
            float* p1 = &C[(size_t)(r + 8) * ldc + cc];
            if (accflag) {
                float2 o0 = *(float2*)p0, o1 = *(float2*)p1;
                v0.x += o0.x; v0.y += o0.y; v1.x += o1.x; v1.y += o1.y;
            }
            *(float2*)p0 = v0;
            *(float2*)p1 = v1;
        }
}

// ---------------------------------------------------------------------------
// Fused attention v3.
// Block = (128 q-rows, head), 256 threads = 8 warps; warp w owns rows
// w*16 + {gr, gr+8} for the full 64-col K chunk (max/sum warp-local).
// Pass A: online row max/sum over 8 K chunks (double-buffered K).
// Pass B: recompute S chunk, normalize -> write attn once, PV via
//         register-fragment path (S accum == PV A-frag), V double-buffered.
// Dyn smem: Q[128][36w] + 2*K[64][36w] + 2*V[32][72w] = 55296 B
// ---------------------------------------------------------------------------
__global__ void __launch_bounds__(256) attn_fused3(
    const float* __restrict__ qkv, const float* __restrict__ topo,
    float* __restrict__ attn, float* __restrict__ ztan) {
    extern __shared__ unsigned sm[];
    unsigned* Qs = sm;                         // 128*36
    unsigned* Kb[2] = {sm + 4608, sm + 4608 + 2304};
    unsigned* Vb[2] = {sm + 9216, sm + 9216 + 2304};

    int q0 = blockIdx.x * 128;
    int head = blockIdx.y;
    int b = head >> 3, h = head & 7;
    int tid = threadIdx.x, lane = tid & 31, w = tid >> 5;
    int gr = lane >> 2, lq = lane & 3;
    int r0 = w * 16 + gr, r1 = r0 + 8;         // local rows
    const float* qbase = qkv + (size_t)b * 512 * 1536 + h * 64;
    const float* kbase = qbase + 512;
    const float* vbase = qbase + 1024;
    const float scale = 0.125f;
    const float* topo0 = topo + (size_t)(q0 + r0) * 512;
    const float* topo1 = topo + (size_t)(q0 + r1) * 512;

    // ---- load Q tile (128x64) ----
#pragma unroll
    for (int q = 0; q < 8; q++) {
        int i = tid + q * 256;
        int r = i >> 4, c4 = (i & 15) * 4;
        float4 f = *(const float4*)(qbase + (size_t)(q0 + r) * 1536 + c4);
        *(uint2*)&Qs[r * 36 + c4 / 2] = make_uint2(pk2(f.x, f.y), pk2(f.z, f.w));
    }
    // preload K[0]
#pragma unroll
    for (int q = 0; q < 4; q++) {
        int i = tid + q * 256;
        int r = i >> 4, c4 = (i & 15) * 4;
        float4 f = *(const float4*)(kbase + (size_t)r * 1536 + c4);
        *(uint2*)&Kb[0][r * 36 + c4 / 2] = make_uint2(pk2(f.x, f.y), pk2(f.z, f.w));
    }
    __syncthreads();

    float m0 = -1e30f, m1 = -1e30f, s0 = 0.f, s1 = 0.f;

    // ---------------- Pass A: row max & sum ----------------
    for (int nc = 0; nc < 8; nc++) {
        const unsigned* Ks = Kb[nc & 1];
        float4 kf[4];
        if (nc < 7) {
#pragma unroll
            for (int q = 0; q < 4; q++) {
                int i = tid + q * 256;
                int r = i >> 4, c4 = (i & 15) * 4;
                kf[q] = *(const float4*)(kbase + (size_t)((nc + 1) * 64 + r) * 1536 + c4);
            }
        }
        float c[8][4];
#pragma unroll
        for (int j = 0; j < 8; j++)
#pragma unroll
            for (int q = 0; q < 4; q++) c[j][q] = 0.f;
#pragma unroll
        for (int ks = 0; ks < 64; ks += 16) {
            int kw = ks >> 1;
            unsigned a[4];
            a[0] = Qs[r0 * 36 + kw + lq];
            a[1] = Qs[r1 * 36 + kw + lq];
            a[2] = Qs[r0 * 36 + kw + 4 + lq];
            a[3] = Qs[r1 * 36 + kw + 4 + lq];
#pragma unroll
            for (int nb = 0; nb < 8; nb++) {
                int n = nb * 8 + gr;
                unsigned bb[2];
                bb[0] = Ks[n * 36 + kw + lq];
                bb[1] = Ks[n * 36 + kw + 4 + lq];
                mma16(c[nb], a, bb);
            }
        }
        float v[8][4];
        float tm0 = -1e30f, tm1 = -1e30f;
#pragma unroll
        for (int nb = 0; nb < 8; nb++) {
            int gc = nc * 64 + nb * 8 + 2 * lq;
            float2 t0 = *(const float2*)&topo0[gc];
            float2 t1 = *(const float2*)&topo1[gc];
            v[nb][0] = c[nb][0] * scale + t0.x;
            v[nb][1] = c[nb][1] * scale + t0.y;
            v[nb][2] = c[nb][2] * scale + t1.x;
            v[nb][3] = c[nb][3] * scale + t1.y;
            tm0 = fmaxf(tm0, fmaxf(v[nb][0], v[nb][1]));
            tm1 = fmaxf(tm1, fmaxf(v[nb][2], v[nb][3]));
        }
        tm0 = fmaxf(tm0, __shfl_xor_sync(0xffffffffu, tm0, 1));
        tm0 = fmaxf(tm0, __shfl_xor_sync(0xffffffffu, tm0, 2));
        tm1 = fmaxf(tm1, __shfl_xor_sync(0xffffffffu, tm1, 1));
        tm1 = fmaxf(tm1, __shfl_xor_sync(0xffffffffu, tm1, 2));
        float nm0 = fmaxf(m0, tm0), nm1 = fmaxf(m1, tm1);
        float ps0 = 0.f, ps1 = 0.f;
#pragma unroll
        for (int nb = 0; nb < 8; nb++) {
            ps0 += __expf(v[nb][0] - nm0) + __expf(v[nb][1] - nm0);
            ps1 += __expf(v[nb][2] - nm1) + __expf(v[nb][3] - nm1);
        }
        ps0 += __shfl_xor_sync(0xffffffffu, ps0, 1);
        ps0 += __shfl_xor_sync(0xffffffffu, ps0, 2);
        ps1 += __shfl_xor_sync(0xffffffffu, ps1, 1);
        ps1 += __shfl_xor_sync(0xffffffffu, ps1, 2);
        s0 = s0 * __expf(m0 - nm0) + ps0;
        s1 = s1 * __expf(m1 - nm1) + ps1;
        m0 = nm0; m1 = nm1;
        if (nc < 7) {
            unsigned* Kn = Kb[(nc + 1) & 1];
#pragma unroll
            for (int q = 0; q < 4; q++) {
                int i = tid + q * 256;
                int r = i >> 4, c4 = (i & 15) * 4;
                *(uint2*)&Kn[r * 36 + c4 / 2] =
                    make_uint2(pk2(kf[q].x, kf[q].y), pk2(kf[q].z, kf[q].w));
            }
        }
        __syncthreads();
    }
    float inv0 = 1.0f / s0, inv1 = 1.0f / s1;

    // preload K[0], V[0] into buffer 0
#pragma unroll
    for (int q = 0; q < 4; q++) {
        int i = tid + q * 256;
        int r = i >> 4, c4 = (i & 15) * 4;
        float4 f = *(const float4*)(kbase + (size_t)r * 1536 + c4);
        *(uint2*)&Kb[0][r * 36 + c4 / 2] = make_uint2(pk2(f.x, f.y), pk2(f.z, f.w));
    }
#pragma unroll
    for (int q = 0; q < 4; q++) {
        int i = tid + q * 256;
        int kp = i >> 5, n2 = (i & 31) * 2;
        const float* vr = vbase + (size_t)(2 * kp) * 1536 + n2;
        float2 f0 = *(const float2*)vr;
        float2 f1 = *(const float2*)(vr + 1536);
        *(uint2*)&Vb[0][kp * 72 + n2] = make_uint2(pk2(f0.x, f1.x), pk2(f0.y, f1.y));
    }
    __syncthreads();

    // ---------------- Pass B: normalize + write attn + PV ----------------
    float z[8][4];
#pragma unroll
    for (int j = 0; j < 8; j++)
#pragma unroll
        for (int q = 0; q < 4; q++) z[j][q] = 0.f;
    float* attn_base = attn + ((size_t)head * 512 + q0) * 512;

    for (int kc = 0; kc < 8; kc++) {
        const unsigned* Ks = Kb[kc & 1];
        const unsigned* Vs = Vb[kc & 1];
        float4 kf[4];
        float2 vf0[4], vf1[4];
        if (kc < 7) {
#pragma unroll
            for (int q = 0; q < 4; q++) {
                int i = tid + q * 256;
                int r = i >> 4, c4 = (i & 15) * 4;
                kf[q] = *(const float4*)(kbase + (size_t)((kc + 1) * 64 + r) * 1536 + c4);
            }
#pragma unroll
            for (int q = 0; q < 4; q++) {
                int i = tid + q * 256;
                int kp = i >> 5, n2 = (i & 31) * 2;
                const float* vr = vbase + (size_t)((kc + 1) * 64 + 2 * kp) * 1536 + n2;
                vf0[q] = *(const float2*)vr;
                vf1[q] = *(const float2*)(vr + 1536);
            }
        }
        // recompute S chunk
        float c[8][4];
#pragma unroll
        for (int j = 0; j < 8; j++)
#pragma unroll
            for (int q = 0; q < 4; q++) c[j][q] = 0.f;
#pragma unroll
        for (int ks = 0; ks < 64; ks += 16) {
            int kw = ks >> 1;
            unsigned a[4];
            a[0] = Qs[r0 * 36 + kw + lq];
            a[1] = Qs[r1 * 36 + kw + lq];
            a[2] = Qs[r0 * 36 + kw + 4 + lq];
            a[3] = Qs[r1 * 36 + kw + 4 + lq];
#pragma unroll
            for (int nb = 0; nb < 8; nb++) {
                int n = nb * 8 + gr;
                unsigned bb[2];
                bb[0] = Ks[n * 36 + kw + lq];
                bb[1] = Ks[n * 36 + kw + 4 + lq];
                mma16(c[nb], a, bb);
            }
        }
        // normalize, write attn, keep p in c[][]
#pragma unroll
        for (int nb = 0; nb < 8; nb++) {
            int gc = kc * 64 + nb * 8 + 2 * lq;
            float2 t0 = *(const float2*)&topo0[gc];
            float2 t1 = *(const float2*)&topo1[gc];
            c[nb][0] = __expf(c[nb][0] * scale + t0.x - m0) * inv0;
            c[nb][1] = __expf(c[nb][1] * scale + t0.y - m0) * inv0;
            c[nb][2] = __expf(c[nb][2] * scale + t1.x - m1) * inv1;
            c[nb][3] = __expf(c[nb][3] * scale + t1.y - m1) * inv1;
            *(float2*)&attn_base[(size_t)r0 * 512 + gc] = make_float2(c[nb][0], c[nb][1]);
            *(float2*)&attn_base[(size_t)r1 * 512 + gc] = make_float2(c[nb][2], c[nb][3]);
        }
        // PV: S accum fragments ARE the A fragments
#pragma unroll
        for (int kb = 0; kb < 4; kb++) {
            unsigned pa[4];
            pa[0] = pk2(c[2 * kb][0], c[2 * kb][1]);
            pa[1] = pk2(c[2 * kb][2], c[2 * kb][3]);
            pa[2] = pk2(c[2 * kb + 1][0], c[2 * kb + 1][1]);
            pa[3] = pk2(c[2 * kb + 1][2], c[2 * kb + 1][3]);
            int kw = kb * 8;
#pragma unroll
            for (int nb = 0; nb < 8; nb++) {
                int n = nb * 8 + gr;
                unsigned bb[2];
                bb[0] = Vs[(kw + lq) * 72 + n];
                bb[1] = Vs[(kw + lq + 4) * 72 + n];
                mma16(z[nb], pa, bb);
            }
        }
        if (kc < 7) {
            unsigned* Kn = Kb[(kc + 1) & 1];
            unsigned* Vn = Vb[(kc + 1) & 1];
#pragma unroll
            for (int q = 0; q < 4; q++) {
                int i = tid + q * 256;
                int r = i >> 4, c4 = (i & 15) * 4;
                *(uint2*)&Kn[r * 36 + c4 / 2] =
                    make_uint2(pk2(kf[q].x, kf[q].y), pk2(kf[q].z, kf[q].w));
            }
#pragma unroll
            for (int q = 0; q < 4; q++) {
                int i = tid + q * 256;
                int kp = i >> 5, n2 = (i & 31) * 2;
                *(uint2*)&Vn[kp * 72 + n2] =
                    make_uint2(pk2(vf0[q].x, vf1[q].x), pk2(vf0[q].y, vf1[q].y));
            }
        }
        __syncthreads();
    }
    // epilogue -> ztan (B,J,E)
    int orow = b * 512 + q0 + r0;
#pragma unroll
    for (int nb = 0; nb < 8; nb++) {
        int col = h * 64 + nb * 8 + 2 * lq;
        *(float2*)&ztan[(size_t)orow * 512 + col] = make_float2(z[nb][0], z[nb][1]);
        *(float2*)&ztan[(size_t)(orow + 8) * 512 + col] = make_float2(z[nb][2], z[nb][3]);
    }
}

// ---------------------------------------------------------------------------
extern "C" void kernel_launch(void* const* d_in, const int* in_sizes, int n_in,
                              void* d_out, int out_size) {
    const float* x       = (const float*)d_in[0];
    const float* x_vel   = (const float*)d_in[1];
    const float* topo    = (const float*)d_in[2];
    const float* W_qkv   = (const float*)d_in[3];
    const float* W_vproj = (const float*)d_in[4];
    const float* W_proj  = (const float*)d_in[5];
    const float* b_proj  = (const float*)d_in[6];

    float* out    = (float*)d_out;
    float* z_man  = out;                                   // 32*512*513
    float* attn   = out + (size_t)BB * JJ * (EE + 1);      // 32*8*512*512
    float* x_tan  = attn + (size_t)BB * HH * JJ * JJ;      // 32*512*512

    void *pq = nullptr, *pz = nullptr, *pz2 = nullptr;
    cudaGetSymbolAddress(&pq, g_qkv);
    cudaGetSymbolAddress(&pz, g_ztan);
    cudaGetSymbolAddress(&pz2, g_ztan2);
    float* qkv   = (float*)pq;
    float* ztan  = (float*)pz;
    float* ztan2 = (float*)pz2;   // staging for v_tan first, then out-proj result

    const int fused_smem = 13824 * 4;   // 55296 B
    static int attr_set = 0;
    if (!attr_set) {
        cudaFuncSetAttribute(attn_fused3, cudaFuncAttributeMaxDynamicSharedMemorySize,
                             fused_smem);
        attr_set = 1;
    }

    // 1. log-map -> x_tan; stage v_tan aligned
    xtan_kernel<<<MROWS, 128>>>(x, x_tan);
    vel_copy_kernel<<<MROWS, 128>>>(x_vel, ztan2);

    // 2. qkv = x_tan @ W_qkv^T   (M=16384, N=1536, K=512)
    {
        dim3 g(1536 / 128, MROWS / 128);
        gemm_nt_bf<<<g, 256>>>(x_tan, 512, W_qkv, 512, qkv, 1536, 512, nullptr, 0);
    }
    // 3. k += v_tan @ W_vproj^T  (accumulate into k slab; aligned now)
    {
        dim3 g(512 / 128, MROWS / 128);
        gemm_nt_bf<<<g, 256>>>(ztan2, 512, W_vproj, 512, qkv + 512, 1536, 512,
                               nullptr, 1);
    }
    // 4-6. fused S + softmax + PV
    {
        dim3 g(4, BB * HH);
        attn_fused3<<<g, 256, fused_smem>>>(qkv, topo, attn, ztan);
    }
    // 7. out-proj: ztan2 = ztan @ W_proj^T + b_proj
    {
        dim3 g(512 / 128, MROWS / 128);
        gemm_nt_bf<<<g, 256>>>(ztan, 512, W_proj, 512, ztan2, 512, 512, b_proj, 0);
    }
    // 8. exp-map -> z_manifold
    expmap_kernel<<<MROWS, 128>>>(ztan2, z_man);
}

// round 6
// speedup vs baseline: 2.6000x; 1.1030x over previous
#include <cuda_runtime.h>
#include <cuda_bf16.h>
#include <math.h>

// Problem constants
#define BB 32
#define JJ 512
#define EE 512
#define HH 8
#define MROWS (BB*JJ)          // 16384
#define EPSF 1e-7f

// Scratch (device globals; no allocation allowed)
__device__ float g_qkv[MROWS * 3 * EE];   // [16384,1536]  q|k|v per row
__device__ float g_ztan[MROWS * EE];      // attn @ v, (B,J,E)
__device__ float g_ztan2[MROWS * EE];     // out-proj result; also vel staging early

// ---------------------------------------------------------------------------
// bf16 helpers
// ---------------------------------------------------------------------------
__device__ __forceinline__ unsigned pk2(float lo, float hi) {
    __nv_bfloat162 t = __floats2bfloat162_rn(lo, hi);
    return *reinterpret_cast<unsigned*>(&t);
}

__device__ __forceinline__ void mma16(float (&c)[4], const unsigned (&a)[4],
                                      const unsigned (&b)[2]) {
    asm volatile(
        "mma.sync.aligned.m16n8k16.row.col.f32.bf16.bf16.f32 "
        "{%0,%1,%2,%3},{%4,%5,%6,%7},{%8,%9},{%0,%1,%2,%3};"
        : "+f"(c[0]), "+f"(c[1]), "+f"(c[2]), "+f"(c[3])
        : "r"(a[0]), "r"(a[1]), "r"(a[2]), "r"(a[3]), "r"(b[0]), "r"(b[1]));
}

// ---------------------------------------------------------------------------
// log_map0_spatial
// ---------------------------------------------------------------------------
__global__ void xtan_kernel(const float* __restrict__ x, float* __restrict__ xt) {
    int row = blockIdx.x;
    const float* p = x + (size_t)row * 513;
    float* o = xt + (size_t)row * 512;
    int t = threadIdx.x;  // 128 threads
    float v[4];
    float s = 0.f;
#pragma unroll
    for (int q = 0; q < 4; q++) { v[q] = p[1 + t + q * 128]; s += v[q] * v[q]; }
#pragma unroll
    for (int o2 = 16; o2 > 0; o2 >>= 1) s += __shfl_xor_sync(0xffffffffu, s, o2);
    __shared__ float sb[4];
    if ((t & 31) == 0) sb[t >> 5] = s;
    __syncthreads();
    float tot = sb[0] + sb[1] + sb[2] + sb[3];
    float nrm = sqrtf(tot);
    float x0 = fmaxf(p[0], 1.0f + 1e-7f);
    float theta = acoshf(x0);
    float sc = theta / fmaxf(nrm, EPSF);
#pragma unroll
    for (int q = 0; q < 4; q++) o[t + q * 128] = sc * v[q];
}

// ---------------------------------------------------------------------------
// stage x_vel[...,1:] into aligned [rows,512] buffer
// ---------------------------------------------------------------------------
__global__ void vel_copy_kernel(const float* __restrict__ xv, float* __restrict__ o) {
    int row = blockIdx.x;
    const float* p = xv + (size_t)row * 513 + 1;
    float* q = o + (size_t)row * 512;
    int t = threadIdx.x;  // 128
#pragma unroll
    for (int i = 0; i < 4; i++) q[t + i * 128] = p[t + i * 128];
}

// ---------------------------------------------------------------------------
// exp_map0
// ---------------------------------------------------------------------------
__global__ void expmap_kernel(const float* __restrict__ zt, float* __restrict__ zm) {
    int row = blockIdx.x;
    const float* p = zt + (size_t)row * 512;
    float* o = zm + (size_t)row * 513;
    int t = threadIdx.x;
    float v[4];
    float s = 0.f;
#pragma unroll
    for (int q = 0; q < 4; q++) { v[q] = p[t + q * 128]; s += v[q] * v[q]; }
#pragma unroll
    for (int o2 = 16; o2 > 0; o2 >>= 1) s += __shfl_xor_sync(0xffffffffu, s, o2);
    __shared__ float sb[4];
    if ((t & 31) == 0) sb[t >> 5] = s;
    __syncthreads();
    float tot = sb[0] + sb[1] + sb[2] + sb[3];
    float nrm = sqrtf(tot);
    float sc = sinhf(nrm) / fmaxf(nrm, EPSF);
    if (t == 0) o[0] = coshf(nrm);
#pragma unroll
    for (int q = 0; q < 4; q++) o[1 + t + q * 128] = sc * v[q];
}

// ---------------------------------------------------------------------------
// Dense TC GEMM (bf16), double-buffered:
// C[M,N] (+)= A[M,K] * W[N,K]^T (+bias)
// BM=BN=128, BK=32, 256 threads = 8 warps (2x4), warp tile 64x32.
// Per iteration: prefetch next chunk (LDG->cvt->regs), MMA current smem buf,
// store regs to alternate buf, one __syncthreads.
// ---------------------------------------------------------------------------
__global__ void __launch_bounds__(256) gemm_nt_bf(
    const float* __restrict__ A, int lda,
    const float* __restrict__ W, int ldb,
    float* __restrict__ C, int ldc, int K,
    const float* __restrict__ bias, int accflag) {
    __shared__ unsigned As[2][128 * 20];
    __shared__ unsigned Bs[2][128 * 20];
    int tid = threadIdx.x, lane = tid & 31, w = tid >> 5;
    int gr = lane >> 2, lq = lane & 3;
    int m0w = (w >> 2) * 64, n0w = (w & 3) * 32;
    const float* Ab = A + (size_t)blockIdx.y * 128 * lda;
    const float* Wb = W + (size_t)blockIdx.x * 128 * ldb;
    // per-thread load coords (4 rows apart in r; same for A and B)
    int lr = tid >> 3, lc4 = (tid & 7) * 4;        // row 0..31 (+32*q), col 0..28
    float c[4][4][4];
#pragma unroll
    for (int i = 0; i < 4; i++)
#pragma unroll
        for (int j = 0; j < 4; j++)
#pragma unroll
            for (int q = 0; q < 4; q++) c[i][j][q] = 0.f;

    // initial fill of buffer 0
#pragma unroll
    for (int q = 0; q < 4; q++) {
        int r = lr + q * 32;
        float4 f = *(const float4*)(Ab + (size_t)r * lda + lc4);
        *(uint2*)&As[0][r * 20 + lc4 / 2] = make_uint2(pk2(f.x, f.y), pk2(f.z, f.w));
        float4 g = *(const float4*)(Wb + (size_t)r * ldb + lc4);
        *(uint2*)&Bs[0][r * 20 + lc4 / 2] = make_uint2(pk2(g.x, g.y), pk2(g.z, g.w));
    }
    __syncthreads();

    int nsteps = K / 32;
    for (int kstep = 0; kstep < nsteps; kstep++) {
        int buf = kstep & 1;
        const unsigned* Ac = As[buf];
        const unsigned* Bc = Bs[buf];
        uint2 pa[4], pb[4];
        if (kstep + 1 < nsteps) {
            int k0 = (kstep + 1) * 32;
#pragma unroll
            for (int q = 0; q < 4; q++) {
                int r = lr + q * 32;
                float4 f = *(const float4*)(Ab + (size_t)r * lda + k0 + lc4);
                pa[q] = make_uint2(pk2(f.x, f.y), pk2(f.z, f.w));
                float4 g = *(const float4*)(Wb + (size_t)r * ldb + k0 + lc4);
                pb[q] = make_uint2(pk2(g.x, g.y), pk2(g.z, g.w));
            }
        }
#pragma unroll
        for (int ks = 0; ks < 32; ks += 16) {
            int kw = ks >> 1;
            unsigned af[4][4], bf[4][2];
#pragma unroll
            for (int ma = 0; ma < 4; ma++) {
                int m = m0w + ma * 16 + gr;
                af[ma][0] = Ac[m * 20 + kw + lq];
                af[ma][1] = Ac[(m + 8) * 20 + kw + lq];
                af[ma][2] = Ac[m * 20 + kw + 4 + lq];
                af[ma][3] = Ac[(m + 8) * 20 + kw + 4 + lq];
            }
#pragma unroll
            for (int nb = 0; nb < 4; nb++) {
                int n = n0w + nb * 8 + gr;
                bf[nb][0] = Bc[n * 20 + kw + lq];
                bf[nb][1] = Bc[n * 20 + kw + 4 + lq];
            }
#pragma unroll
            for (int ma = 0; ma < 4; ma++)
#pragma unroll
                for (int nb = 0; nb < 4; nb++) mma16(c[ma][nb], af[ma], bf[nb]);
        }
        if (kstep + 1 < nsteps) {
            unsigned* An = As[buf ^ 1];
            unsigned* Bn = Bs[buf ^ 1];
#pragma unroll
            for (int q = 0; q < 4; q++) {
                int r = lr + q * 32;
                *(uint2*)&An[r * 20 + lc4 / 2] = pa[q];
                *(uint2*)&Bn[r * 20 + lc4 / 2] = pb[q];
            }
        }
        __syncthreads();
    }
    int row0 = blockIdx.y * 128 + m0w;
    int col0 = blockIdx.x * 128 + n0w;
#pragma unroll
    for (int ma = 0; ma < 4; ma++)
#pragma unroll
        for (int nb = 0; nb < 4; nb++) {
            int r = row0 + ma * 16 + gr;
            int cc = col0 + nb * 8 + 2 * lq;
            float2 v0 = make_float2(c[ma][nb][0], c[ma][nb][1]);
            float2 v1 = make_float2(c[ma][nb][2], c[ma][nb][3]);
            if (bias) {
                float bx = bias[cc], by = bias[cc + 1];
                v0.x += bx; v0.y += by; v1.x += bx; v1.y += by;
            }
            float* p0 = &C[(size_t)r * ldc + cc];
            float* p1 = &C[(size_t)(r + 8) * ldc + cc];
            if (accflag) {
                float2 o0 = *(float2*)p0, o1 = *(float2*)p1;
                v0.x += o0.x; v0.y += o0.y; v1.x += o1.x; v1.y += o1.y;
            }
            *(float2*)p0 = v0;
            *(float2*)p1 = v1;
        }
}

// ---------------------------------------------------------------------------
// Fused attention v3 (unchanged from round 5 winner).
// ---------------------------------------------------------------------------
__global__ void __launch_bounds__(256) attn_fused3(
    const float* __restrict__ qkv, const float* __restrict__ topo,
    float* __restrict__ attn, float* __restrict__ ztan) {
    extern __shared__ unsigned sm[];
    unsigned* Qs = sm;                         // 128*36
    unsigned* Kb[2] = {sm + 4608, sm + 4608 + 2304};
    unsigned* Vb[2] = {sm + 9216, sm + 9216 + 2304};

    int q0 = blockIdx.x * 128;
    int head = blockIdx.y;
    int b = head >> 3, h = head & 7;
    int tid = threadIdx.x, lane = tid & 31, w = tid >> 5;
    int gr = lane >> 2, lq = lane & 3;
    int r0 = w * 16 + gr, r1 = r0 + 8;         // local rows
    const float* qbase = qkv + (size_t)b * 512 * 1536 + h * 64;
    const float* kbase = qbase + 512;
    const float* vbase = qbase + 1024;
    const float scale = 0.125f;
    const float* topo0 = topo + (size_t)(q0 + r0) * 512;
    const float* topo1 = topo + (size_t)(q0 + r1) * 512;

    // ---- load Q tile (128x64) ----
#pragma unroll
    for (int q = 0; q < 8; q++) {
        int i = tid + q * 256;
        int r = i >> 4, c4 = (i & 15) * 4;
        float4 f = *(const float4*)(qbase + (size_t)(q0 + r) * 1536 + c4);
        *(uint2*)&Qs[r * 36 + c4 / 2] = make_uint2(pk2(f.x, f.y), pk2(f.z, f.w));
    }
    // preload K[0]
#pragma unroll
    for (int q = 0; q < 4; q++) {
        int i = tid + q * 256;
        int r = i >> 4, c4 = (i & 15) * 4;
        float4 f = *(const float4*)(kbase + (size_t)r * 1536 + c4);
        *(uint2*)&Kb[0][r * 36 + c4 / 2] = make_uint2(pk2(f.x, f.y), pk2(f.z, f.w));
    }
    __syncthreads();

    float m0 = -1e30f, m1 = -1e30f, s0 = 0.f, s1 = 0.f;

    // ---------------- Pass A: row max & sum ----------------
    for (int nc = 0; nc < 8; nc++) {
        const unsigned* Ks = Kb[nc & 1];
        float4 kf[4];
        if (nc < 7) {
#pragma unroll
            for (int q = 0; q < 4; q++) {
                int i = tid + q * 256;
                int r = i >> 4, c4 = (i & 15) * 4;
                kf[q] = *(const float4*)(kbase + (size_t)((nc + 1) * 64 + r) * 1536 + c4);
            }
        }
        float c[8][4];
#pragma unroll
        for (int j = 0; j < 8; j++)
#pragma unroll
            for (int q = 0; q < 4; q++) c[j][q] = 0.f;
#pragma unroll
        for (int ks = 0; ks < 64; ks += 16) {
            int kw = ks >> 1;
            unsigned a[4];
            a[0] = Qs[r0 * 36 + kw + lq];
            a[1] = Qs[r1 * 36 + kw + lq];
            a[2] = Qs[r0 * 36 + kw + 4 + lq];
            a[3] = Qs[r1 * 36 + kw + 4 + lq];
#pragma unroll
            for (int nb = 0; nb < 8; nb++) {
                int n = nb * 8 + gr;
                unsigned bb[2];
                bb[0] = Ks[n * 36 + kw + lq];
                bb[1] = Ks[n * 36 + kw + 4 + lq];
                mma16(c[nb], a, bb);
            }
        }
        float v[8][4];
        float tm0 = -1e30f, tm1 = -1e30f;
#pragma unroll
        for (int nb = 0; nb < 8; nb++) {
            int gc = nc * 64 + nb * 8 + 2 * lq;
            float2 t0 = *(const float2*)&topo0[gc];
            float2 t1 = *(const float2*)&topo1[gc];
            v[nb][0] = c[nb][0] * scale + t0.x;
            v[nb][1] = c[nb][1] * scale + t0.y;
            v[nb][2] = c[nb][2] * scale + t1.x;
            v[nb][3] = c[nb][3] * scale + t1.y;
            tm0 = fmaxf(tm0, fmaxf(v[nb][0], v[nb][1]));
            tm1 = fmaxf(tm1, fmaxf(v[nb][2], v[nb][3]));
        }
        tm0 = fmaxf(tm0, __shfl_xor_sync(0xffffffffu, tm0, 1));
        tm0 = fmaxf(tm0, __shfl_xor_sync(0xffffffffu, tm0, 2));
        tm1 = fmaxf(tm1, __shfl_xor_sync(0xffffffffu, tm1, 1));
        tm1 = fmaxf(tm1, __shfl_xor_sync(0xffffffffu, tm1, 2));
        float nm0 = fmaxf(m0, tm0), nm1 = fmaxf(m1, tm1);
        float ps0 = 0.f, ps1 = 0.f;
#pragma unroll
        for (int nb = 0; nb < 8; nb++) {
            ps0 += __expf(v[nb][0] - nm0) + __expf(v[nb][1] - nm0);
            ps1 += __expf(v[nb][2] - nm1) + __expf(v[nb][3] - nm1);
        }
        ps0 += __shfl_xor_sync(0xffffffffu, ps0, 1);
        ps0 += __shfl_xor_sync(0xffffffffu, ps0, 2);
        ps1 += __shfl_xor_sync(0xffffffffu, ps1, 1);
        ps1 += __shfl_xor_sync(0xffffffffu, ps1, 2);
        s0 = s0 * __expf(m0 - nm0) + ps0;
        s1 = s1 * __expf(m1 - nm1) + ps1;
        m0 = nm0; m1 = nm1;
        if (nc < 7) {
            unsigned* Kn = Kb[(nc + 1) & 1];
#pragma unroll
            for (int q = 0; q < 4; q++) {
                int i = tid + q * 256;
                int r = i >> 4, c4 = (i & 15) * 4;
                *(uint2*)&Kn[r * 36 + c4 / 2] =
                    make_uint2(pk2(kf[q].x, kf[q].y), pk2(kf[q].z, kf[q].w));
            }
        }
        __syncthreads();
    }
    float inv0 = 1.0f / s0, inv1 = 1.0f / s1;

    // preload K[0], V[0] into buffer 0
#pragma unroll
    for (int q = 0; q < 4; q++) {
        int i = tid + q * 256;
        int r = i >> 4, c4 = (i & 15) * 4;
        float4 f = *(const float4*)(kbase + (size_t)r * 1536 + c4);
        *(uint2*)&Kb[0][r * 36 + c4 / 2] = make_uint2(pk2(f.x, f.y), pk2(f.z, f.w));
    }
#pragma unroll
    for (int q = 0; q < 4; q++) {
        int i = tid + q * 256;
        int kp = i >> 5, n2 = (i & 31) * 2;
        const float* vr = vbase + (size_t)(2 * kp) * 1536 + n2;
        float2 f0 = *(const float2*)vr;
        float2 f1 = *(const float2*)(vr + 1536);
        *(uint2*)&Vb[0][kp * 72 + n2] = make_uint2(pk2(f0.x, f1.x), pk2(f0.y, f1.y));
    }
    __syncthreads();

    // ---------------- Pass B: normalize + write attn + PV ----------------
    float z[8][4];
#pragma unroll
    for (int j = 0; j < 8; j++)
#pragma unroll
        for (int q = 0; q < 4; q++) z[j][q] = 0.f;
    float* attn_base = attn + ((size_t)head * 512 + q0) * 512;

    for (int kc = 0; kc < 8; kc++) {
        const unsigned* Ks = Kb[kc & 1];
        const unsigned* Vs = Vb[kc & 1];
        float4 kf[4];
        float2 vf0[4], vf1[4];
        if (kc < 7) {
#pragma unroll
            for (int q = 0; q < 4; q++) {
                int i = tid + q * 256;
                int r = i >> 4, c4 = (i & 15) * 4;
                kf[q] = *(const float4*)(kbase + (size_t)((kc + 1) * 64 + r) * 1536 + c4);
            }
#pragma unroll
            for (int q = 0; q < 4; q++) {
                int i = tid + q * 256;
                int kp = i >> 5, n2 = (i & 31) * 2;
                const float* vr = vbase + (size_t)((kc + 1) * 64 + 2 * kp) * 1536 + n2;
                vf0[q] = *(const float2*)vr;
                vf1[q] = *(const float2*)(vr + 1536);
            }
        }
        // recompute S chunk
        float c[8][4];
#pragma unroll
        for (int j = 0; j < 8; j++)
#pragma unroll
            for (int q = 0; q < 4; q++) c[j][q] = 0.f;
#pragma unroll
        for (int ks = 0; ks < 64; ks += 16) {
            int kw = ks >> 1;
            unsigned a[4];
            a[0] = Qs[r0 * 36 + kw + lq];
            a[1] = Qs[r1 * 36 + kw + lq];
            a[2] = Qs[r0 * 36 + kw + 4 + lq];
            a[3] = Qs[r1 * 36 + kw + 4 + lq];
#pragma unroll
            for (int nb = 0; nb < 8; nb++) {
                int n = nb * 8 + gr;
                unsigned bb[2];
                bb[0] = Ks[n * 36 + kw + lq];
                bb[1] = Ks[n * 36 + kw + 4 + lq];
                mma16(c[nb], a, bb);
            }
        }
        // normalize, write attn, keep p in c[][]
#pragma unroll
        for (int nb = 0; nb < 8; nb++) {
            int gc = kc * 64 + nb * 8 + 2 * lq;
            float2 t0 = *(const float2*)&topo0[gc];
            float2 t1 = *(const float2*)&topo1[gc];
            c[nb][0] = __expf(c[nb][0] * scale + t0.x - m0) * inv0;
            c[nb][1] = __expf(c[nb][1] * scale + t0.y - m0) * inv0;
            c[nb][2] = __expf(c[nb][2] * scale + t1.x - m1) * inv1;
            c[nb][3] = __expf(c[nb][3] * scale + t1.y - m1) * inv1;
            *(float2*)&attn_base[(size_t)r0 * 512 + gc] = make_float2(c[nb][0], c[nb][1]);
            *(float2*)&attn_base[(size_t)r1 * 512 + gc] = make_float2(c[nb][2], c[nb][3]);
        }
        // PV: S accum fragments ARE the A fragments
#pragma unroll
        for (int kb = 0; kb < 4; kb++) {
            unsigned pa[4];
            pa[0] = pk2(c[2 * kb][0], c[2 * kb][1]);
            pa[1] = pk2(c[2 * kb][2], c[2 * kb][3]);
            pa[2] = pk2(c[2 * kb + 1][0], c[2 * kb + 1][1]);
            pa[3] = pk2(c[2 * kb + 1][2], c[2 * kb + 1][3]);
            int kw = kb * 8;
#pragma unroll
            for (int nb = 0; nb < 8; nb++) {
                int n = nb * 8 + gr;
                unsigned bb[2];
                bb[0] = Vs[(kw + lq) * 72 + n];
                bb[1] = Vs[(kw + lq + 4) * 72 + n];
                mma16(z[nb], pa, bb);
            }
        }
        if (kc < 7) {
            unsigned* Kn = Kb[(kc + 1) & 1];
            unsigned* Vn = Vb[(kc + 1) & 1];
#pragma unroll
            for (int q = 0; q < 4; q++) {
                int i = tid + q * 256;
                int r = i >> 4, c4 = (i & 15) * 4;
                *(uint2*)&Kn[r * 36 + c4 / 2] =
                    make_uint2(pk2(kf[q].x, kf[q].y), pk2(kf[q].z, kf[q].w));
            }
#pragma unroll
            for (int q = 0; q < 4; q++) {
                int i = tid + q * 256;
                int kp = i >> 5, n2 = (i & 31) * 2;
                *(uint2*)&Vn[kp * 72 + n2] =
                    make_uint2(pk2(vf0[q].x, vf1[q].x), pk2(vf0[q].y, vf1[q].y));
            }
        }
        __syncthreads();
    }
    // epilogue -> ztan (B,J,E)
    int orow = b * 512 + q0 + r0;
#pragma unroll
    for (int nb = 0; nb < 8; nb++) {
        int col = h * 64 + nb * 8 + 2 * lq;
        *(float2*)&ztan[(size_t)orow * 512 + col] = make_float2(z[nb][0], z[nb][1]);
        *(float2*)&ztan[(size_t)(orow + 8) * 512 + col] = make_float2(z[nb][2], z[nb][3]);
    }
}

// ---------------------------------------------------------------------------
extern "C" void kernel_launch(void* const* d_in, const int* in_sizes, int n_in,
                              void* d_out, int out_size) {
    const float* x       = (const float*)d_in[0];
    const float* x_vel   = (const float*)d_in[1];
    const float* topo    = (const float*)d_in[2];
    const float* W_qkv   = (const float*)d_in[3];
    const float* W_vproj = (const float*)d_in[4];
    const float* W_proj  = (const float*)d_in[5];
    const float* b_proj  = (const float*)d_in[6];

    float* out    = (float*)d_out;
    float* z_man  = out;                                   // 32*512*513
    float* attn   = out + (size_t)BB * JJ * (EE + 1);      // 32*8*512*512
    float* x_tan  = attn + (size_t)BB * HH * JJ * JJ;      // 32*512*512

    void *pq = nullptr, *pz = nullptr, *pz2 = nullptr;
    cudaGetSymbolAddress(&pq, g_qkv);
    cudaGetSymbolAddress(&pz, g_ztan);
    cudaGetSymbolAddress(&pz2, g_ztan2);
    float* qkv   = (float*)pq;
    float* ztan  = (float*)pz;
    float* ztan2 = (float*)pz2;   // staging for v_tan first, then out-proj result

    const int fused_smem = 13824 * 4;   // 55296 B
    static int attr_set = 0;
    if (!attr_set) {
        cudaFuncSetAttribute(attn_fused3, cudaFuncAttributeMaxDynamicSharedMemorySize,
                             fused_smem);
        attr_set = 1;
    }

    // 1. log-map -> x_tan; stage v_tan aligned
    xtan_kernel<<<MROWS, 128>>>(x, x_tan);
    vel_copy_kernel<<<MROWS, 128>>>(x_vel, ztan2);

    // 2. qkv = x_tan @ W_qkv^T   (M=16384, N=1536, K=512)
    {
        dim3 g(1536 / 128, MROWS / 128);
        gemm_nt_bf<<<g, 256>>>(x_tan, 512, W_qkv, 512, qkv, 1536, 512, nullptr, 0);
    }
    // 3. k += v_tan @ W_vproj^T  (accumulate into k slab; aligned)
    {
        dim3 g(512 / 128, MROWS / 128);
        gemm_nt_bf<<<g, 256>>>(ztan2, 512, W_vproj, 512, qkv + 512, 1536, 512,
                               nullptr, 1);
    }
    // 4-6. fused S + softmax + PV
    {
        dim3 g(4, BB * HH);
        attn_fused3<<<g, 256, fused_smem>>>(qkv, topo, attn, ztan);
    }
    // 7. out-proj: ztan2 = ztan @ W_proj^T + b_proj
    {
        dim3 g(512 / 128, MROWS / 128);
        gemm_nt_bf<<<g, 256>>>(ztan, 512, W_proj, 512, ztan2, 512, 512, b_proj, 0);
    }
    // 8. exp-map -> z_manifold
    expmap_kernel<<<MROWS, 128>>>(ztan2, z_man);
}

// round 7
// speedup vs baseline: 2.8750x; 1.1058x over previous
#include <cuda_runtime.h>
#include <cuda_bf16.h>
#include <math.h>

// Problem constants
#define BB 32
#define JJ 512
#define EE 512
#define HH 8
#define MROWS (BB*JJ)          // 16384
#define EPSF 1e-7f

// Scratch (device globals; no allocation allowed). bf16 stored packed in unsigned.
__device__ unsigned g_qkv_bf[MROWS * 768];    // [16384,1536] bf16  q|k|v
__device__ unsigned g_xt_bf[MROWS * 256];     // x_tan bf16
__device__ unsigned g_vel_bf[MROWS * 256];    // v_tan bf16
__device__ unsigned g_zt_bf[MROWS * 256];     // attn@V bf16 (B,J,E)
__device__ unsigned g_w_bf[655360];           // wqkv(393216) | wvproj(131072) | wproj(131072) words
__device__ float    g_ztan2[MROWS * EE];      // out-proj result fp32

// ---------------------------------------------------------------------------
// helpers
// ---------------------------------------------------------------------------
__device__ __forceinline__ unsigned pk2(float lo, float hi) {
    __nv_bfloat162 t = __floats2bfloat162_rn(lo, hi);
    return *reinterpret_cast<unsigned*>(&t);
}

__device__ __forceinline__ void mma16(float (&c)[4], const unsigned (&a)[4],
                                      const unsigned (&b)[2]) {
    asm volatile(
        "mma.sync.aligned.m16n8k16.row.col.f32.bf16.bf16.f32 "
        "{%0,%1,%2,%3},{%4,%5,%6,%7},{%8,%9},{%0,%1,%2,%3};"
        : "+f"(c[0]), "+f"(c[1]), "+f"(c[2]), "+f"(c[3])
        : "r"(a[0]), "r"(a[1]), "r"(a[2]), "r"(a[3]), "r"(b[0]), "r"(b[1]));
}

__device__ __forceinline__ void cp16(void* smem_dst, const void* gmem_src) {
    unsigned d = (unsigned)__cvta_generic_to_shared(smem_dst);
    asm volatile("cp.async.cg.shared.global [%0], [%1], 16;" :: "r"(d), "l"(gmem_src));
}
__device__ __forceinline__ void cp_commit() {
    asm volatile("cp.async.commit_group;");
}
__device__ __forceinline__ void cp_wait1() {
    asm volatile("cp.async.wait_group 1;");
}

// ---------------------------------------------------------------------------
// f32 -> packed bf16 convert (nwords pairs)
// ---------------------------------------------------------------------------
__global__ void f2bf_kernel(const float* __restrict__ in, unsigned* __restrict__ out,
                            int nwords) {
    int i = blockIdx.x * 256 + threadIdx.x;
    if (i < nwords) {
        float2 f = ((const float2*)in)[i];
        out[i] = pk2(f.x, f.y);
    }
}

// ---------------------------------------------------------------------------
// log_map0_spatial: fp32 output (x_tan) + bf16 side copy
// ---------------------------------------------------------------------------
__global__ void xtan_kernel(const float* __restrict__ x, float* __restrict__ xt,
                            unsigned* __restrict__ xtb) {
    int row = blockIdx.x;
    const float* p = x + (size_t)row * 513;
    float* o = xt + (size_t)row * 512;
    __nv_bfloat16* ob = (__nv_bfloat16*)(xtb + (size_t)row * 256);
    int t = threadIdx.x;  // 128 threads
    float v[4];
    float s = 0.f;
#pragma unroll
    for (int q = 0; q < 4; q++) { v[q] = p[1 + t + q * 128]; s += v[q] * v[q]; }
#pragma unroll
    for (int o2 = 16; o2 > 0; o2 >>= 1) s += __shfl_xor_sync(0xffffffffu, s, o2);
    __shared__ float sb[4];
    if ((t & 31) == 0) sb[t >> 5] = s;
    __syncthreads();
    float tot = sb[0] + sb[1] + sb[2] + sb[3];
    float nrm = sqrtf(tot);
    float x0 = fmaxf(p[0], 1.0f + 1e-7f);
    float theta = acoshf(x0);
    float sc = theta / fmaxf(nrm, EPSF);
#pragma unroll
    for (int q = 0; q < 4; q++) {
        float val = sc * v[q];
        o[t + q * 128] = val;
        ob[t + q * 128] = __float2bfloat16(val);
    }
}

// ---------------------------------------------------------------------------
// stage x_vel[...,1:] as bf16
// ---------------------------------------------------------------------------
__global__ void vel_copy_kernel(const float* __restrict__ xv, unsigned* __restrict__ ob) {
    int row = blockIdx.x;
    const float* p = xv + (size_t)row * 513 + 1;
    __nv_bfloat16* q = (__nv_bfloat16*)(ob + (size_t)row * 256);
    int t = threadIdx.x;  // 128
#pragma unroll
    for (int i = 0; i < 4; i++) q[t + i * 128] = __float2bfloat16(p[t + i * 128]);
}

// ---------------------------------------------------------------------------
// exp_map0
// ---------------------------------------------------------------------------
__global__ void expmap_kernel(const float* __restrict__ zt, float* __restrict__ zm) {
    int row = blockIdx.x;
    const float* p = zt + (size_t)row * 512;
    float* o = zm + (size_t)row * 513;
    int t = threadIdx.x;
    float v[4];
    float s = 0.f;
#pragma unroll
    for (int q = 0; q < 4; q++) { v[q] = p[t + q * 128]; s += v[q] * v[q]; }
#pragma unroll
    for (int o2 = 16; o2 > 0; o2 >>= 1) s += __shfl_xor_sync(0xffffffffu, s, o2);
    __shared__ float sb[4];
    if ((t & 31) == 0) sb[t >> 5] = s;
    __syncthreads();
    float tot = sb[0] + sb[1] + sb[2] + sb[3];
    float nrm = sqrtf(tot);
    float sc = sinhf(nrm) / fmaxf(nrm, EPSF);
    if (t == 0) o[0] = coshf(nrm);
#pragma unroll
    for (int q = 0; q < 4; q++) o[1 + t + q * 128] = sc * v[q];
}

// ---------------------------------------------------------------------------
// bf16 GEMM, cp.async 3-stage: C[M,N] = A[M,K] * W[N,K]^T (+bias)
// A/W are bf16 with row stride 512 halves; K may be 1024 split across
// (A1,W1 | A2,W2) at Ksplit=512. BM=BN=128, BK=32, 256 thr, warp 64x32.
// remap: blocks with ncol>=512 map W row & C col to +512 (q|v combined GEMM).
// Out: Cb packed-bf16 (ldcw words) or Cf fp32 (ldc floats, +bias).
// Dyn smem: 3 stages x (A+B) x 128x40 halves = 61440 B
// ---------------------------------------------------------------------------
__global__ void __launch_bounds__(256) gemm_bf(
    const __nv_bfloat16* __restrict__ A1, const __nv_bfloat16* __restrict__ A2,
    const __nv_bfloat16* __restrict__ W1, const __nv_bfloat16* __restrict__ W2,
    int K, int remap,
    unsigned* __restrict__ Cb, int ldcw,
    float* __restrict__ Cf, int ldc, const float* __restrict__ bias) {
    extern __shared__ unsigned gsm[];   // word view; stage s: A at s*5120, B at s*5120+2560
    int tid = threadIdx.x, lane = tid & 31, w = tid >> 5;
    int gr = lane >> 2, lq = lane & 3;
    int m0w = (w >> 2) * 64, n0w = (w & 3) * 32;
    int arow = blockIdx.y * 128;
    int ncol = blockIdx.x * 128;
    int wrow = (remap && ncol >= 512) ? ncol + 512 : ncol;
    const __nv_bfloat16* A1b = A1 + (size_t)arow * 512;
    const __nv_bfloat16* A2b = A2 + (size_t)arow * 512;
    const __nv_bfloat16* W1b = W1 + (size_t)wrow * 512;
    const __nv_bfloat16* W2b = W2 + (size_t)ncol * 512;
    int lr0 = tid >> 2, lcs = (tid & 3) * 8;   // q=0 row, halves seg

    float c[4][4][4];
#pragma unroll
    for (int i = 0; i < 4; i++)
#pragma unroll
        for (int j = 0; j < 4; j++)
#pragma unroll
            for (int q = 0; q < 4; q++) c[i][j][q] = 0.f;

    int nsteps = K / 32;
    // preload stages 0,1
#pragma unroll
    for (int st = 0; st < 2; st++) {
        if (st < nsteps) {
            int k0 = st * 32;
            const __nv_bfloat16* As = (k0 < 512) ? A1b + k0 : A2b + (k0 - 512);
            const __nv_bfloat16* Ws = (k0 < 512) ? W1b + k0 : W2b + (k0 - 512);
            __nv_bfloat16* sA = (__nv_bfloat16*)(gsm + st * 5120);
            __nv_bfloat16* sB = (__nv_bfloat16*)(gsm + st * 5120 + 2560);
#pragma unroll
            for (int q = 0; q < 2; q++) {
                int r = lr0 + q * 64;
                cp16(sA + r * 40 + lcs, As + (size_t)r * 512 + lcs);
                cp16(sB + r * 40 + lcs, Ws + (size_t)r * 512 + lcs);
            }
        }
        cp_commit();
    }

    for (int kstep = 0; kstep < nsteps; kstep++) {
        cp_wait1();
        __syncthreads();
        // issue stage kstep+2
        if (kstep + 2 < nsteps) {
            int k0 = (kstep + 2) * 32;
            const __nv_bfloat16* As = (k0 < 512) ? A1b + k0 : A2b + (k0 - 512);
            const __nv_bfloat16* Ws = (k0 < 512) ? W1b + k0 : W2b + (k0 - 512);
            int st = (kstep + 2) % 3;
            __nv_bfloat16* sA = (__nv_bfloat16*)(gsm + st * 5120);
            __nv_bfloat16* sB = (__nv_bfloat16*)(gsm + st * 5120 + 2560);
#pragma unroll
            for (int q = 0; q < 2; q++) {
                int r = lr0 + q * 64;
                cp16(sA + r * 40 + lcs, As + (size_t)r * 512 + lcs);
                cp16(sB + r * 40 + lcs, Ws + (size_t)r * 512 + lcs);
            }
        }
        cp_commit();
        const unsigned* Ac = gsm + (kstep % 3) * 5120;
        const unsigned* Bc = Ac + 2560;
#pragma unroll
        for (int ks = 0; ks < 32; ks += 16) {
            int kw = ks >> 1;
            unsigned af[4][4], bf[4][2];
#pragma unroll
            for (int ma = 0; ma < 4; ma++) {
                int m = m0w + ma * 16 + gr;
                af[ma][0] = Ac[m * 20 + kw + lq];
                af[ma][1] = Ac[(m + 8) * 20 + kw + lq];
                af[ma][2] = Ac[m * 20 + kw + 4 + lq];
                af[ma][3] = Ac[(m + 8) * 20 + kw + 4 + lq];
            }
#pragma unroll
            for (int nb = 0; nb < 4; nb++) {
                int n = n0w + nb * 8 + gr;
                bf[nb][0] = Bc[n * 20 + kw + lq];
                bf[nb][1] = Bc[n * 20 + kw + 4 + lq];
            }
#pragma unroll
            for (int ma = 0; ma < 4; ma++)
#pragma unroll
                for (int nb = 0; nb < 4; nb++) mma16(c[ma][nb], af[ma], bf[nb]);
        }
    }
    int row0 = arow + m0w;
    int col0 = wrow + n0w;   // remapped output base
#pragma unroll
    for (int ma = 0; ma < 4; ma++)
#pragma unroll
        for (int nb = 0; nb < 4; nb++) {
            int r = row0 + ma * 16 + gr;
            int cc = col0 + nb * 8 + 2 * lq;
            if (Cb) {
                Cb[(size_t)r * ldcw + (cc >> 1)] = pk2(c[ma][nb][0], c[ma][nb][1]);
                Cb[(size_t)(r + 8) * ldcw + (cc >> 1)] = pk2(c[ma][nb][2], c[ma][nb][3]);
            } else {
                float2 v0 = make_float2(c[ma][nb][0], c[ma][nb][1]);
                float2 v1 = make_float2(c[ma][nb][2], c[ma][nb][3]);
                float bx = bias[cc], by = bias[cc + 1];
                v0.x += bx; v0.y += by; v1.x += bx; v1.y += by;
                *(float2*)&Cf[(size_t)r * ldc + cc] = v0;
                *(float2*)&Cf[(size_t)(r + 8) * ldc + cc] = v1;
            }
        }
}

// ---------------------------------------------------------------------------
// Fused attention v4: bf16 qkv input, bf16 ztan output.
// Block = (128 q-rows, head), 256 threads = 8 warps; warp w owns rows
// w*16 + {gr, gr+8}. Pass A: online max/sum; Pass B: recompute, write attn,
// PV via register-fragment path. K/V double-buffered with reg prefetch.
// Dyn smem: Q[128*36w] + 2*K[64*36w] + 2*V[32*72w] = 55296 B
// ---------------------------------------------------------------------------
__global__ void __launch_bounds__(256) attn_fused4(
    const unsigned* __restrict__ qkvb, const float* __restrict__ topo,
    float* __restrict__ attn, unsigned* __restrict__ ztb) {
    extern __shared__ unsigned sm[];
    unsigned* Qs = sm;                         // 128*36
    unsigned* Kb[2] = {sm + 4608, sm + 4608 + 2304};
    unsigned* Vb[2] = {sm + 9216, sm + 9216 + 2304};

    int q0 = blockIdx.x * 128;
    int head = blockIdx.y;
    int b = head >> 3, h = head & 7;
    int tid = threadIdx.x, lane = tid & 31, w = tid >> 5;
    int gr = lane >> 2, lq = lane & 3;
    int r0 = w * 16 + gr, r1 = r0 + 8;
    const __nv_bfloat16* qkvh = (const __nv_bfloat16*)qkvb;
    const __nv_bfloat16* qbase = qkvh + (size_t)b * 512 * 1536 + h * 64;
    const __nv_bfloat16* kbase = qbase + 512;
    const __nv_bfloat16* vbase = qbase + 1024;
    const float scale = 0.125f;
    const float* topo0 = topo + (size_t)(q0 + r0) * 512;
    const float* topo1 = topo + (size_t)(q0 + r1) * 512;

    // ---- load Q tile (128x64 bf16) ----
#pragma unroll
    for (int q = 0; q < 8; q++) {
        int i = tid + q * 256;
        int r = i >> 4, c4 = (i & 15) * 4;
        *(uint2*)&Qs[r * 36 + c4 / 2] =
            *(const uint2*)(qbase + (size_t)(q0 + r) * 1536 + c4);
    }
    // preload K[0]
#pragma unroll
    for (int q = 0; q < 4; q++) {
        int i = tid + q * 256;
        int r = i >> 4, c4 = (i & 15) * 4;
        *(uint2*)&Kb[0][r * 36 + c4 / 2] = *(const uint2*)(kbase + (size_t)r * 1536 + c4);
    }
    __syncthreads();

    float m0 = -1e30f, m1 = -1e30f, s0 = 0.f, s1 = 0.f;

    // ---------------- Pass A ----------------
    for (int nc = 0; nc < 8; nc++) {
        const unsigned* Ks = Kb[nc & 1];
        uint2 kf[4];
        if (nc < 7) {
#pragma unroll
            for (int q = 0; q < 4; q++) {
                int i = tid + q * 256;
                int r = i >> 4, c4 = (i & 15) * 4;
                kf[q] = *(const uint2*)(kbase + (size_t)((nc + 1) * 64 + r) * 1536 + c4);
            }
        }
        float c[8][4];
#pragma unroll
        for (int j = 0; j < 8; j++)
#pragma unroll
            for (int q = 0; q < 4; q++) c[j][q] = 0.f;
#pragma unroll
        for (int ks = 0; ks < 64; ks += 16) {
            int kw = ks >> 1;
            unsigned a[4];
            a[0] = Qs[r0 * 36 + kw + lq];
            a[1] = Qs[r1 * 36 + kw + lq];
            a[2] = Qs[r0 * 36 + kw + 4 + lq];
            a[3] = Qs[r1 * 36 + kw + 4 + lq];
#pragma unroll
            for (int nb = 0; nb < 8; nb++) {
                int n = nb * 8 + gr;
                unsigned bb[2];
                bb[0] = Ks[n * 36 + kw + lq];
                bb[1] = Ks[n * 36 + kw + 4 + lq];
                mma16(c[nb], a, bb);
            }
        }
        float v[8][4];
        float tm0 = -1e30f, tm1 = -1e30f;
#pragma unroll
        for (int nb = 0; nb < 8; nb++) {
            int gc = nc * 64 + nb * 8 + 2 * lq;
            float2 t0 = *(const float2*)&topo0[gc];
            float2 t1 = *(const float2*)&topo1[gc];
            v[nb][0] = c[nb][0] * scale + t0.x;
            v[nb][1] = c[nb][1] * scale + t0.y;
            v[nb][2] = c[nb][2] * scale + t1.x;
            v[nb][3] = c[nb][3] * scale + t1.y;
            tm0 = fmaxf(tm0, fmaxf(v[nb][0], v[nb][1]));
            tm1 = fmaxf(tm1, fmaxf(v[nb][2], v[nb][3]));
        }
        tm0 = fmaxf(tm0, __shfl_xor_sync(0xffffffffu, tm0, 1));
        tm0 = fmaxf(tm0, __shfl_xor_sync(0xffffffffu, tm0, 2));
        tm1 = fmaxf(tm1, __shfl_xor_sync(0xffffffffu, tm1, 1));
        tm1 = fmaxf(tm1, __shfl_xor_sync(0xffffffffu, tm1, 2));
        float nm0 = fmaxf(m0, tm0), nm1 = fmaxf(m1, tm1);
        float ps0 = 0.f, ps1 = 0.f;
#pragma unroll
        for (int nb = 0; nb < 8; nb++) {
            ps0 += __expf(v[nb][0] - nm0) + __expf(v[nb][1] - nm0);
            ps1 += __expf(v[nb][2] - nm1) + __expf(v[nb][3] - nm1);
        }
        ps0 += __shfl_xor_sync(0xffffffffu, ps0, 1);
        ps0 += __shfl_xor_sync(0xffffffffu, ps0, 2);
        ps1 += __shfl_xor_sync(0xffffffffu, ps1, 1);
        ps1 += __shfl_xor_sync(0xffffffffu, ps1, 2);
        s0 = s0 * __expf(m0 - nm0) + ps0;
        s1 = s1 * __expf(m1 - nm1) + ps1;
        m0 = nm0; m1 = nm1;
        if (nc < 7) {
            unsigned* Kn = Kb[(nc + 1) & 1];
#pragma unroll
            for (int q = 0; q < 4; q++) {
                int i = tid + q * 256;
                int r = i >> 4, c4 = (i & 15) * 4;
                *(uint2*)&Kn[r * 36 + c4 / 2] = kf[q];
            }
        }
        __syncthreads();
    }
    float inv0 = 1.0f / s0, inv1 = 1.0f / s1;

    // preload K[0], V[0]
#pragma unroll
    for (int q = 0; q < 4; q++) {
        int i = tid + q * 256;
        int r = i >> 4, c4 = (i & 15) * 4;
        *(uint2*)&Kb[0][r * 36 + c4 / 2] = *(const uint2*)(kbase + (size_t)r * 1536 + c4);
    }
#pragma unroll
    for (int q = 0; q < 4; q++) {
        int i = tid + q * 256;
        int kp = i >> 5, n2 = (i & 31) * 2;
        unsigned u0 = *(const unsigned*)(vbase + (size_t)(2 * kp) * 1536 + n2);
        unsigned u1 = *(const unsigned*)(vbase + (size_t)(2 * kp + 1) * 1536 + n2);
        Vb[0][kp * 72 + n2] = __byte_perm(u0, u1, 0x5410);
        Vb[0][kp * 72 + n2 + 1] = __byte_perm(u0, u1, 0x7632);
    }
    __syncthreads();

    // ---------------- Pass B ----------------
    float z[8][4];
#pragma unroll
    for (int j = 0; j < 8; j++)
#pragma unroll
        for (int q = 0; q < 4; q++) z[j][q] = 0.f;
    float* attn_base = attn + ((size_t)head * 512 + q0) * 512;

    for (int kc = 0; kc < 8; kc++) {
        const unsigned* Ks = Kb[kc & 1];
        const unsigned* Vs = Vb[kc & 1];
        uint2 kf[4];
        unsigned vu0[4], vu1[4];
        if (kc < 7) {
#pragma unroll
            for (int q = 0; q < 4; q++) {
                int i = tid + q * 256;
                int r = i >> 4, c4 = (i & 15) * 4;
                kf[q] = *(const uint2*)(kbase + (size_t)((kc + 1) * 64 + r) * 1536 + c4);
            }
#pragma unroll
            for (int q = 0; q < 4; q++) {
                int i = tid + q * 256;
                int kp = i >> 5, n2 = (i & 31) * 2;
                vu0[q] = *(const unsigned*)(vbase + (size_t)((kc + 1) * 64 + 2 * kp) * 1536 + n2);
                vu1[q] = *(const unsigned*)(vbase + (size_t)((kc + 1) * 64 + 2 * kp + 1) * 1536 + n2);
            }
        }
        // recompute S chunk
        float c[8][4];
#pragma unroll
        for (int j = 0; j < 8; j++)
#pragma unroll
            for (int q = 0; q < 4; q++) c[j][q] = 0.f;
#pragma unroll
        for (int ks = 0; ks < 64; ks += 16) {
            int kw = ks >> 1;
            unsigned a[4];
            a[0] = Qs[r0 * 36 + kw + lq];
            a[1] = Qs[r1 * 36 + kw + lq];
            a[2] = Qs[r0 * 36 + kw + 4 + lq];
            a[3] = Qs[r1 * 36 + kw + 4 + lq];
#pragma unroll
            for (int nb = 0; nb < 8; nb++) {
                int n = nb * 8 + gr;
                unsigned bb[2];
                bb[0] = Ks[n * 36 + kw + lq];
                bb[1] = Ks[n * 36 + kw + 4 + lq];
                mma16(c[nb], a, bb);
            }
        }
        // normalize, write attn
#pragma unroll
        for (int nb = 0; nb < 8; nb++) {
            int gc = kc * 64 + nb * 8 + 2 * lq;
            float2 t0 = *(const float2*)&topo0[gc];
            float2 t1 = *(const float2*)&topo1[gc];
            c[nb][0] = __expf(c[nb][0] * scale + t0.x - m0) * inv0;
            c[nb][1] = __expf(c[nb][1] * scale + t0.y - m0) * inv0;
            c[nb][2] = __expf(c[nb][2] * scale + t1.x - m1) * inv1;
            c[nb][3] = __expf(c[nb][3] * scale + t1.y - m1) * inv1;
            *(float2*)&attn_base[(size_t)r0 * 512 + gc] = make_float2(c[nb][0], c[nb][1]);
            *(float2*)&attn_base[(size_t)r1 * 512 + gc] = make_float2(c[nb][2], c[nb][3]);
        }
        // PV
#pragma unroll
        for (int kb = 0; kb < 4; kb++) {
            unsigned pa[4];
            pa[0] = pk2(c[2 * kb][0], c[2 * kb][1]);
            pa[1] = pk2(c[2 * kb][2], c[2 * kb][3]);
            pa[2] = pk2(c[2 * kb + 1][0], c[2 * kb + 1][1]);
            pa[3] = pk2(c[2 * kb + 1][2], c[2 * kb + 1][3]);
            int kw = kb * 8;
#pragma unroll
            for (int nb = 0; nb < 8; nb++) {
                int n = nb * 8 + gr;
                unsigned bb[2];
                bb[0] = Vs[(kw + lq) * 72 + n];
                bb[1] = Vs[(kw + lq + 4) * 72 + n];
                mma16(z[nb], pa, bb);
            }
        }
        if (kc < 7) {
            unsigned* Kn = Kb[(kc + 1) & 1];
            unsigned* Vn = Vb[(kc + 1) & 1];
#pragma unroll
            for (int q = 0; q < 4; q++) {
                int i = tid + q * 256;
                int r = i >> 4, c4 = (i & 15) * 4;
                *(uint2*)&Kn[r * 36 + c4 / 2] = kf[q];
            }
#pragma unroll
            for (int q = 0; q < 4; q++) {
                int i = tid + q * 256;
                int kp = i >> 5, n2 = (i & 31) * 2;
                Vn[kp * 72 + n2] = __byte_perm(vu0[q], vu1[q], 0x5410);
                Vn[kp * 72 + n2 + 1] = __byte_perm(vu0[q], vu1[q], 0x7632);
            }
        }
        __syncthreads();
    }
    // epilogue -> zt_bf (B,J,E) packed bf16
    int orow = b * 512 + q0 + r0;
#pragma unroll
    for (int nb = 0; nb < 8; nb++) {
        int col = h * 64 + nb * 8 + 2 * lq;
        ztb[(size_t)orow * 256 + (col >> 1)] = pk2(z[nb][0], z[nb][1]);
        ztb[(size_t)(orow + 8) * 256 + (col >> 1)] = pk2(z[nb][2], z[nb][3]);
    }
}

// ---------------------------------------------------------------------------
extern "C" void kernel_launch(void* const* d_in, const int* in_sizes, int n_in,
                              void* d_out, int out_size) {
    const float* x       = (const float*)d_in[0];
    const float* x_vel   = (const float*)d_in[1];
    const float* topo    = (const float*)d_in[2];
    const float* W_qkv   = (const float*)d_in[3];
    const float* W_vproj = (const float*)d_in[4];
    const float* W_proj  = (const float*)d_in[5];
    const float* b_proj  = (const float*)d_in[6];

    float* out    = (float*)d_out;
    float* z_man  = out;                                   // 32*512*513
    float* attn   = out + (size_t)BB * JJ * (EE + 1);      // 32*8*512*512
    float* x_tan  = attn + (size_t)BB * HH * JJ * JJ;      // 32*512*512

    void *pq, *pxt, *pvel, *pzt, *pw, *pz2;
    cudaGetSymbolAddress(&pq, g_qkv_bf);
    cudaGetSymbolAddress(&pxt, g_xt_bf);
    cudaGetSymbolAddress(&pvel, g_vel_bf);
    cudaGetSymbolAddress(&pzt, g_zt_bf);
    cudaGetSymbolAddress(&pw, g_w_bf);
    cudaGetSymbolAddress(&pz2, g_ztan2);
    unsigned* qkvb = (unsigned*)pq;
    unsigned* xtb  = (unsigned*)pxt;
    unsigned* velb = (unsigned*)pvel;
    unsigned* ztb  = (unsigned*)pzt;
    unsigned* wqkvb   = (unsigned*)pw;              // 393216 words
    unsigned* wvprojb = wqkvb + 393216;             // 131072 words
    unsigned* wprojb  = wvprojb + 131072;           // 131072 words
    float* ztan2 = (float*)pz2;

    const int gemm_smem = 61440;
    const int attn_smem = 13824 * 4;   // 55296
    static int attr_set = 0;
    if (!attr_set) {
        cudaFuncSetAttribute(gemm_bf, cudaFuncAttributeMaxDynamicSharedMemorySize,
                             gemm_smem);
        cudaFuncSetAttribute(attn_fused4, cudaFuncAttributeMaxDynamicSharedMemorySize,
                             attn_smem);
        attr_set = 1;
    }

    // 0. weight conversions
    f2bf_kernel<<<1536, 256>>>(W_qkv, wqkvb, 393216);
    f2bf_kernel<<<512, 256>>>(W_vproj, wvprojb, 131072);
    f2bf_kernel<<<512, 256>>>(W_proj, wprojb, 131072);

    // 1. log-map -> x_tan (output) + bf16 copy; vel -> bf16
    xtan_kernel<<<MROWS, 128>>>(x, x_tan, xtb);
    vel_copy_kernel<<<MROWS, 128>>>(x_vel, velb);

    const __nv_bfloat16* xth = (const __nv_bfloat16*)xtb;
    const __nv_bfloat16* velh = (const __nv_bfloat16*)velb;
    const __nv_bfloat16* wqkvh = (const __nv_bfloat16*)wqkvb;
    const __nv_bfloat16* wvprojh = (const __nv_bfloat16*)wvprojb;
    const __nv_bfloat16* wprojh = (const __nv_bfloat16*)wprojb;
    const __nv_bfloat16* zth = (const __nv_bfloat16*)ztb;

    // 2. q|v slabs: N=1024 remapped (cols>=512 -> +512), K=512
    {
        dim3 g(8, MROWS / 128);
        gemm_bf<<<g, 256, gemm_smem>>>(xth, xth, wqkvh, wqkvh, 512, 1,
                                       qkvb, 768, nullptr, 0, nullptr);
    }
    // 3. k slab: concat-K GEMM, K=1024 (x_tan|v_tan @ Wk|Wvproj)
    {
        dim3 g(4, MROWS / 128);
        gemm_bf<<<g, 256, gemm_smem>>>(xth, velh, wqkvh + 512 * 512, wvprojh, 1024, 0,
                                       qkvb + 256, 768, nullptr, 0, nullptr);
    }
    // 4-6. fused S + softmax + PV
    {
        dim3 g(4, BB * HH);
        attn_fused4<<<g, 256, attn_smem>>>(qkvb, topo, attn, ztb);
    }
    // 7. out-proj: ztan2 = ztan @ W_proj^T + b_proj (fp32 out)
    {
        dim3 g(4, MROWS / 128);
        gemm_bf<<<g, 256, gemm_smem>>>(zth, zth, wprojh, wprojh, 512, 0,
                                       nullptr, 0, ztan2, 512, b_proj);
    }
    // 8. exp-map -> z_manifold
    expmap_kernel<<<MROWS, 128>>>(ztan2, z_man);
}

// round 9
// speedup vs baseline: 3.1487x; 1.0952x over previous
#include <cuda_runtime.h>
#include <cuda_bf16.h>
#include <math.h>

// Problem constants
#define BB 32
#define JJ 512
#define EE 512
#define HH 8
#define MROWS (BB*JJ)          // 16384
#define EPSF 1e-7f

// Scratch (device globals; no allocation allowed). bf16 packed in unsigned.
__device__ unsigned g_qkv_bf[MROWS * 768];    // [16384,1536] bf16  q|k|v
__device__ unsigned g_xt_bf[MROWS * 256];     // x_tan bf16
__device__ unsigned g_vel_bf[MROWS * 256];    // v_tan bf16
__device__ unsigned g_zt_bf[MROWS * 256];     // attn@V bf16 (B,J,E)
__device__ unsigned g_w_bf[655360];           // wqkv | wvproj | wproj words
__device__ float    g_ztan2[MROWS * EE];      // out-proj result fp32
__device__ float2   g_stats[BB * HH * JJ];    // per attn row: (max, 1/sum)

// ---------------------------------------------------------------------------
// helpers
// ---------------------------------------------------------------------------
__device__ __forceinline__ unsigned pk2(float lo, float hi) {
    __nv_bfloat162 t = __floats2bfloat162_rn(lo, hi);
    return *reinterpret_cast<unsigned*>(&t);
}

__device__ __forceinline__ void mma16(float (&c)[4], const unsigned (&a)[4],
                                      const unsigned (&b)[2]) {
    asm volatile(
        "mma.sync.aligned.m16n8k16.row.col.f32.bf16.bf16.f32 "
        "{%0,%1,%2,%3},{%4,%5,%6,%7},{%8,%9},{%0,%1,%2,%3};"
        : "+f"(c[0]), "+f"(c[1]), "+f"(c[2]), "+f"(c[3])
        : "r"(a[0]), "r"(a[1]), "r"(a[2]), "r"(a[3]), "r"(b[0]), "r"(b[1]));
}

__device__ __forceinline__ void cp16(void* smem_dst, const void* gmem_src) {
    unsigned d = (unsigned)__cvta_generic_to_shared(smem_dst);
    asm volatile("cp.async.cg.shared.global [%0], [%1], 16;" :: "r"(d), "l"(gmem_src));
}
__device__ __forceinline__ void cp_commit() { asm volatile("cp.async.commit_group;"); }
__device__ __forceinline__ void cp_wait1() { asm volatile("cp.async.wait_group 1;"); }

__device__ __forceinline__ unsigned s2u(const void* p) {
    return (unsigned)__cvta_generic_to_shared(p);
}
__device__ __forceinline__ void ldm4(unsigned& r0, unsigned& r1, unsigned& r2,
                                     unsigned& r3, unsigned a) {
    asm volatile("ldmatrix.sync.aligned.m8n8.x4.shared.b16 {%0,%1,%2,%3}, [%4];"
                 : "=r"(r0), "=r"(r1), "=r"(r2), "=r"(r3) : "r"(a));
}

// lane offsets for ldmatrix fragments. PITCH = smem row pitch in BYTES.
// A x4: reg0 rows 0-7/k0-7, reg1 rows 8-15/k0-7, reg2 rows 0-7/k8-15, reg3 rows 8-15/k8-15
// B x4 (pair of n8 frags): reg0 n0-7/k0-7(b0), reg1 n0-7/k8-15(b1), reg2 n8-15 b0, reg3 n8-15 b1
__device__ __forceinline__ unsigned laneA_off(int lane, int pitch) {
    int sel = lane >> 3;
    return (unsigned)((((sel & 1) * 8) + (lane & 7)) * pitch + (sel >> 1) * 16);
}
__device__ __forceinline__ unsigned laneB_off(int lane, int pitch) {
    int sel = lane >> 3;
    return (unsigned)((((sel >> 1) * 8) + (lane & 7)) * pitch + (sel & 1) * 16);
}

// ---------------------------------------------------------------------------
// merged f32 -> packed bf16 weight convert
// ---------------------------------------------------------------------------
__global__ void f2bf_all(const float* __restrict__ wqkv, const float* __restrict__ wvp,
                         const float* __restrict__ wpr, unsigned* __restrict__ out) {
    int i = blockIdx.x * 256 + threadIdx.x;   // 0..655359
    const float* src;
    int j;
    if (i < 393216) { src = wqkv; j = i; }
    else if (i < 524288) { src = wvp; j = i - 393216; }
    else { src = wpr; j = i - 524288; }
    float2 f = ((const float2*)src)[j];
    out[i] = pk2(f.x, f.y);
}

// ---------------------------------------------------------------------------
// log_map0_spatial (fp32 + bf16 out) fused with vel bf16 staging
// ---------------------------------------------------------------------------
__global__ void xtan_vel_kernel(const float* __restrict__ x, const float* __restrict__ xv,
                                float* __restrict__ xt, unsigned* __restrict__ xtb,
                                unsigned* __restrict__ velb) {
    int row = blockIdx.x;
    const float* p = x + (size_t)row * 513;
    const float* pv = xv + (size_t)row * 513 + 1;
    float* o = xt + (size_t)row * 512;
    __nv_bfloat16* ob = (__nv_bfloat16*)(xtb + (size_t)row * 256);
    __nv_bfloat16* vb = (__nv_bfloat16*)(velb + (size_t)row * 256);
    int t = threadIdx.x;  // 128
    float v[4];
    float s = 0.f;
#pragma unroll
    for (int q = 0; q < 4; q++) { v[q] = p[1 + t + q * 128]; s += v[q] * v[q]; }
#pragma unroll
    for (int o2 = 16; o2 > 0; o2 >>= 1) s += __shfl_xor_sync(0xffffffffu, s, o2);
    __shared__ float sb[4];
    if ((t & 31) == 0) sb[t >> 5] = s;
    __syncthreads();
    float tot = sb[0] + sb[1] + sb[2] + sb[3];
    float nrm = sqrtf(tot);
    float x0 = fmaxf(p[0], 1.0f + 1e-7f);
    float theta = acoshf(x0);
    float sc = theta / fmaxf(nrm, EPSF);
#pragma unroll
    for (int q = 0; q < 4; q++) {
        float val = sc * v[q];
        o[t + q * 128] = val;
        ob[t + q * 128] = __float2bfloat16(val);
        vb[t + q * 128] = __float2bfloat16(pv[t + q * 128]);
    }
}

// ---------------------------------------------------------------------------
// exp_map0
// ---------------------------------------------------------------------------
__global__ void expmap_kernel(const float* __restrict__ zt, float* __restrict__ zm) {
    int row = blockIdx.x;
    const float* p = zt + (size_t)row * 512;
    float* o = zm + (size_t)row * 513;
    int t = threadIdx.x;
    float v[4];
    float s = 0.f;
#pragma unroll
    for (int q = 0; q < 4; q++) { v[q] = p[t + q * 128]; s += v[q] * v[q]; }
#pragma unroll
    for (int o2 = 16; o2 > 0; o2 >>= 1) s += __shfl_xor_sync(0xffffffffu, s, o2);
    __shared__ float sb[4];
    if ((t & 31) == 0) sb[t >> 5] = s;
    __syncthreads();
    float tot = sb[0] + sb[1] + sb[2] + sb[3];
    float nrm = sqrtf(tot);
    float sc = sinhf(nrm) / fmaxf(nrm, EPSF);
    if (t == 0) o[0] = coshf(nrm);
#pragma unroll
    for (int q = 0; q < 4; q++) o[1 + t + q * 128] = sc * v[q];
}

// ---------------------------------------------------------------------------
// bf16 GEMM, cp.async 3-stage + ldmatrix: C[M,N] = A[M,K] * W[N,K]^T (+bias)
// Smem rows: 32 halves data, pitch 40 halves (80 B) -> conflict-free ldmatrix.
// ---------------------------------------------------------------------------
__global__ void __launch_bounds__(256) gemm_bf(
    const __nv_bfloat16* __restrict__ A1, const __nv_bfloat16* __restrict__ A2,
    const __nv_bfloat16* __restrict__ W1, const __nv_bfloat16* __restrict__ W2,
    int K, int remap,
    unsigned* __restrict__ Cb, int ldcw,
    float* __restrict__ Cf, int ldc, const float* __restrict__ bias) {
    extern __shared__ unsigned gsm[];   // stage s: A at s*5120 words, B at +2560
    int tid = threadIdx.x, lane = tid & 31, w = tid >> 5;
    int gr = lane >> 2, lq = lane & 3;
    int m0w = (w >> 2) * 64, n0w = (w & 3) * 32;
    unsigned lA = laneA_off(lane, 80), lB = laneB_off(lane, 80);
    int arow = blockIdx.y * 128;
    int ncol = blockIdx.x * 128;
    int wrow = (remap && ncol >= 512) ? ncol + 512 : ncol;
    const __nv_bfloat16* A1b = A1 + (size_t)arow * 512;
    const __nv_bfloat16* A2b = A2 + (size_t)arow * 512;
    const __nv_bfloat16* W1b = W1 + (size_t)wrow * 512;
    const __nv_bfloat16* W2b = W2 + (size_t)ncol * 512;
    int lr0 = tid >> 2, lcs = (tid & 3) * 8;

    float c[4][4][4];
#pragma unroll
    for (int i = 0; i < 4; i++)
#pragma unroll
        for (int j = 0; j < 4; j++)
#pragma unroll
            for (int q = 0; q < 4; q++) c[i][j][q] = 0.f;

    int nsteps = K / 32;
#pragma unroll
    for (int st = 0; st < 2; st++) {
        if (st < nsteps) {
            int k0 = st * 32;
            const __nv_bfloat16* As = (k0 < 512) ? A1b + k0 : A2b + (k0 - 512);
            const __nv_bfloat16* Ws = (k0 < 512) ? W1b + k0 : W2b + (k0 - 512);
            __nv_bfloat16* sA = (__nv_bfloat16*)(gsm + st * 5120);
            __nv_bfloat16* sB = (__nv_bfloat16*)(gsm + st * 5120 + 2560);
#pragma unroll
            for (int q = 0; q < 2; q++) {
                int r = lr0 + q * 64;
                cp16(sA + r * 40 + lcs, As + (size_t)r * 512 + lcs);
                cp16(sB + r * 40 + lcs, Ws + (size_t)r * 512 + lcs);
            }
        }
        cp_commit();
    }

    for (int kstep = 0; kstep < nsteps; kstep++) {
        cp_wait1();
        __syncthreads();
        if (kstep + 2 < nsteps) {
            int k0 = (kstep + 2) * 32;
            const __nv_bfloat16* As = (k0 < 512) ? A1b + k0 : A2b + (k0 - 512);
            const __nv_bfloat16* Ws = (k0 < 512) ? W1b + k0 : W2b + (k0 - 512);
            int st = (kstep + 2) % 3;
            __nv_bfloat16* sA = (__nv_bfloat16*)(gsm + st * 5120);
            __nv_bfloat16* sB = (__nv_bfloat16*)(gsm + st * 5120 + 2560);
#pragma unroll
            for (int q = 0; q < 2; q++) {
                int r = lr0 + q * 64;
                cp16(sA + r * 40 + lcs, As + (size_t)r * 512 + lcs);
                cp16(sB + r * 40 + lcs, Ws + (size_t)r * 512 + lcs);
            }
        }
        cp_commit();
        unsigned Au = s2u(gsm + (kstep % 3) * 5120);
        unsigned Bu = Au + 2560 * 4;
#pragma unroll
        for (int ksh = 0; ksh < 32; ksh += 16) {
            unsigned af[4][4], bf[4][2];
#pragma unroll
            for (int ma = 0; ma < 4; ma++)
                ldm4(af[ma][0], af[ma][1], af[ma][2], af[ma][3],
                     Au + (m0w + ma * 16) * 80 + lA + ksh * 2);
#pragma unroll
            for (int nbp = 0; nbp < 2; nbp++)
                ldm4(bf[2 * nbp][0], bf[2 * nbp][1], bf[2 * nbp + 1][0], bf[2 * nbp + 1][1],
                     Bu + (n0w + nbp * 16) * 80 + lB + ksh * 2);
#pragma unroll
            for (int ma = 0; ma < 4; ma++)
#pragma unroll
                for (int nb = 0; nb < 4; nb++) mma16(c[ma][nb], af[ma], bf[nb]);
        }
    }
    int row0 = arow + m0w;
    int col0 = wrow + n0w;
#pragma unroll
    for (int ma = 0; ma < 4; ma++)
#pragma unroll
        for (int nb = 0; nb < 4; nb++) {
            int r = row0 + ma * 16 + gr;
            int cc = col0 + nb * 8 + 2 * lq;
            if (Cb) {
                Cb[(size_t)r * ldcw + (cc >> 1)] = pk2(c[ma][nb][0], c[ma][nb][1]);
                Cb[(size_t)(r + 8) * ldcw + (cc >> 1)] = pk2(c[ma][nb][2], c[ma][nb][3]);
            } else {
                float2 v0 = make_float2(c[ma][nb][0], c[ma][nb][1]);
                float2 v1 = make_float2(c[ma][nb][2], c[ma][nb][3]);
                float bx = bias[cc], by = bias[cc + 1];
                v0.x += bx; v0.y += by; v1.x += bx; v1.y += by;
                *(float2*)&Cf[(size_t)r * ldc + cc] = v0;
                *(float2*)&Cf[(size_t)(r + 8) * ldc + cc] = v1;
            }
        }
}

// ---------------------------------------------------------------------------
// attention stats: per (64-row q-tile, head), 128 threads = 4 warps.
// Q/K tiles: 64 halves data per row, pitch 36 words (144 B) -> conflict-free.
// Dyn smem: Q[64*36w] + 2*K[64*36w] = 27648 B.
// ---------------------------------------------------------------------------
__global__ void __launch_bounds__(128) attn_stats(
    const unsigned* __restrict__ qkvb, const float* __restrict__ topo,
    float2* __restrict__ stats) {
    extern __shared__ unsigned sm[];
    unsigned* Qs = sm;                          // 64*36
    unsigned* Kb[2] = {sm + 2304, sm + 2304 + 2304};

    int q0 = blockIdx.x * 64;
    int head = blockIdx.y;
    int b = head >> 3, h = head & 7;
    int tid = threadIdx.x, lane = tid & 31, w = tid >> 5;   // w 0..3
    int lq = lane & 3;
    unsigned lA = laneA_off(lane, 144), lB = laneB_off(lane, 144);
    int gr = lane >> 2;
    int r0 = w * 16 + gr, r1 = r0 + 8;
    const __nv_bfloat16* qkvh = (const __nv_bfloat16*)qkvb;
    const __nv_bfloat16* qbase = qkvh + (size_t)b * 512 * 1536 + h * 64;
    const __nv_bfloat16* kbase = qbase + 512;
    const float scale = 0.125f;
    const float* topo0 = topo + (size_t)(q0 + r0) * 512;
    const float* topo1 = topo + (size_t)(q0 + r1) * 512;

    // load Q tile 64x64
#pragma unroll
    for (int q = 0; q < 8; q++) {
        int i = tid + q * 128;
        int r = i >> 4, c4 = (i & 15) * 4;
        *(uint2*)&Qs[r * 36 + c4 / 2] = *(const uint2*)(qbase + (size_t)(q0 + r) * 1536 + c4);
    }
    // preload K[0]
#pragma unroll
    for (int q = 0; q < 8; q++) {
        int i = tid + q * 128;
        int r = i >> 4, c4 = (i & 15) * 4;
        *(uint2*)&Kb[0][r * 36 + c4 / 2] = *(const uint2*)(kbase + (size_t)r * 1536 + c4);
    }
    __syncthreads();
    unsigned Qu = s2u(Qs) + (w * 16) * 144 + lA;

    float m0 = -1e30f, m1 = -1e30f, s0 = 0.f, s1 = 0.f;
    for (int nc = 0; nc < 8; nc++) {
        unsigned Ku = s2u(Kb[nc & 1]) + lB;
        uint2 kf[8];
        if (nc < 7) {
#pragma unroll
            for (int q = 0; q < 8; q++) {
                int i = tid + q * 128;
                int r = i >> 4, c4 = (i & 15) * 4;
                kf[q] = *(const uint2*)(kbase + (size_t)((nc + 1) * 64 + r) * 1536 + c4);
            }
        }
        float c[8][4];
#pragma unroll
        for (int j = 0; j < 8; j++)
#pragma unroll
            for (int q = 0; q < 4; q++) c[j][q] = 0.f;
#pragma unroll
        for (int ksh = 0; ksh < 64; ksh += 16) {
            unsigned a[4];
            ldm4(a[0], a[1], a[2], a[3], Qu + ksh * 2);
            unsigned bb[8][2];
#pragma unroll
            for (int nbp = 0; nbp < 4; nbp++)
                ldm4(bb[2 * nbp][0], bb[2 * nbp][1], bb[2 * nbp + 1][0], bb[2 * nbp + 1][1],
                     Ku + nbp * 16 * 144 + ksh * 2);
#pragma unroll
            for (int nb = 0; nb < 8; nb++) mma16(c[nb], a, bb[nb]);
        }
        float tm0 = -1e30f, tm1 = -1e30f;
        float v[8][4];
#pragma unroll
        for (int nb = 0; nb < 8; nb++) {
            int gc = nc * 64 + nb * 8 + 2 * lq;
            float2 t0 = *(const float2*)&topo0[gc];
            float2 t1 = *(const float2*)&topo1[gc];
            v[nb][0] = c[nb][0] * scale + t0.x;
            v[nb][1] = c[nb][1] * scale + t0.y;
            v[nb][2] = c[nb][2] * scale + t1.x;
            v[nb][3] = c[nb][3] * scale + t1.y;
            tm0 = fmaxf(tm0, fmaxf(v[nb][0], v[nb][1]));
            tm1 = fmaxf(tm1, fmaxf(v[nb][2], v[nb][3]));
        }
        tm0 = fmaxf(tm0, __shfl_xor_sync(0xffffffffu, tm0, 1));
        tm0 = fmaxf(tm0, __shfl_xor_sync(0xffffffffu, tm0, 2));
        tm1 = fmaxf(tm1, __shfl_xor_sync(0xffffffffu, tm1, 1));
        tm1 = fmaxf(tm1, __shfl_xor_sync(0xffffffffu, tm1, 2));
        float nm0 = fmaxf(m0, tm0), nm1 = fmaxf(m1, tm1);
        float ps0 = 0.f, ps1 = 0.f;
#pragma unroll
        for (int nb = 0; nb < 8; nb++) {
            ps0 += __expf(v[nb][0] - nm0) + __expf(v[nb][1] - nm0);
            ps1 += __expf(v[nb][2] - nm1) + __expf(v[nb][3] - nm1);
        }
        ps0 += __shfl_xor_sync(0xffffffffu, ps0, 1);
        ps0 += __shfl_xor_sync(0xffffffffu, ps0, 2);
        ps1 += __shfl_xor_sync(0xffffffffu, ps1, 1);
        ps1 += __shfl_xor_sync(0xffffffffu, ps1, 2);
        s0 = s0 * __expf(m0 - nm0) + ps0;
        s1 = s1 * __expf(m1 - nm1) + ps1;
        m0 = nm0; m1 = nm1;
        if (nc < 7) {
            unsigned* Kn = Kb[(nc + 1) & 1];
#pragma unroll
            for (int q = 0; q < 8; q++) {
                int i = tid + q * 128;
                int r = i >> 4, c4 = (i & 15) * 4;
                *(uint2*)&Kn[r * 36 + c4 / 2] = kf[q];
            }
        }
        __syncthreads();
    }
    if (lq == 0) {
        stats[(size_t)head * 512 + q0 + r0] = make_float2(m0, 1.0f / s0);
        stats[(size_t)head * 512 + q0 + r1] = make_float2(m1, 1.0f / s1);
    }
}

// ---------------------------------------------------------------------------
// attention main: recompute S, normalize with stats, write attn (streaming),
// PV via register-fragment path. Block = (128 q-rows, head).
// Dyn smem: Q[128*36] + 2*K[64*36] + 2*V[32*72] = 55296 B
// ---------------------------------------------------------------------------
__global__ void __launch_bounds__(256) attn_main(
    const unsigned* __restrict__ qkvb, const float* __restrict__ topo,
    const float2* __restrict__ stats,
    float* __restrict__ attn, unsigned* __restrict__ ztb) {
    extern __shared__ unsigned sm[];
    unsigned* Qs = sm;                          // 128*36
    unsigned* Kb[2] = {sm + 4608, sm + 4608 + 2304};
    unsigned* Vb[2] = {sm + 9216, sm + 9216 + 2304};

    int q0 = blockIdx.x * 128;
    int head = blockIdx.y;
    int b = head >> 3, h = head & 7;
    int tid = threadIdx.x, lane = tid & 31, w = tid >> 5;
    int gr = lane >> 2, lq = lane & 3;
    unsigned lA = laneA_off(lane, 144), lB = laneB_off(lane, 144);
    int r0 = w * 16 + gr, r1 = r0 + 8;
    const __nv_bfloat16* qkvh = (const __nv_bfloat16*)qkvb;
    const __nv_bfloat16* qbase = qkvh + (size_t)b * 512 * 1536 + h * 64;
    const __nv_bfloat16* kbase = qbase + 512;
    const __nv_bfloat16* vbase = qbase + 1024;
    const float scale = 0.125f;
    const float* topo0 = topo + (size_t)(q0 + r0) * 512;
    const float* topo1 = topo + (size_t)(q0 + r1) * 512;
    float2 st0 = stats[(size_t)head * 512 + q0 + r0];
    float2 st1 = stats[(size_t)head * 512 + q0 + r1];
    float m0 = st0.x, inv0 = st0.y, m1 = st1.x, inv1 = st1.y;

    // load Q tile (128x64)
#pragma unroll
    for (int q = 0; q < 8; q++) {
        int i = tid + q * 256;
        int r = i >> 4, c4 = (i & 15) * 4;
        *(uint2*)&Qs[r * 36 + c4 / 2] = *(const uint2*)(qbase + (size_t)(q0 + r) * 1536 + c4);
    }
    // preload K[0], V[0]
#pragma unroll
    for (int q = 0; q < 4; q++) {
        int i = tid + q * 256;
        int r = i >> 4, c4 = (i & 15) * 4;
        *(uint2*)&Kb[0][r * 36 + c4 / 2] = *(const uint2*)(kbase + (size_t)r * 1536 + c4);
    }
#pragma unroll
    for (int q = 0; q < 4; q++) {
        int i = tid + q * 256;
        int kp = i >> 5, n2 = (i & 31) * 2;
        unsigned u0 = *(const unsigned*)(vbase + (size_t)(2 * kp) * 1536 + n2);
        unsigned u1 = *(const unsigned*)(vbase + (size_t)(2 * kp + 1) * 1536 + n2);
        Vb[0][kp * 72 + n2] = __byte_perm(u0, u1, 0x5410);
        Vb[0][kp * 72 + n2 + 1] = __byte_perm(u0, u1, 0x7632);
    }
    __syncthreads();
    unsigned Qu = s2u(Qs) + (w * 16) * 144 + lA;

    float z[8][4];
#pragma unroll
    for (int j = 0; j < 8; j++)
#pragma unroll
        for (int q = 0; q < 4; q++) z[j][q] = 0.f;
    float* attn_base = attn + ((size_t)head * 512 + q0) * 512;

    for (int kc = 0; kc < 8; kc++) {
        unsigned Ku = s2u(Kb[kc & 1]) + lB;
        const unsigned* Vs = Vb[kc & 1];
        uint2 kf[4];
        unsigned vu0[4], vu1[4];
        if (kc < 7) {
#pragma unroll
            for (int q = 0; q < 4; q++) {
                int i = tid + q * 256;
                int r = i >> 4, c4 = (i & 15) * 4;
                kf[q] = *(const uint2*)(kbase + (size_t)((kc + 1) * 64 + r) * 1536 + c4);
            }
#pragma unroll
            for (int q = 0; q < 4; q++) {
                int i = tid + q * 256;
                int kp = i >> 5, n2 = (i & 31) * 2;
                vu0[q] = *(const unsigned*)(vbase + (size_t)((kc + 1) * 64 + 2 * kp) * 1536 + n2);
                vu1[q] = *(const unsigned*)(vbase + (size_t)((kc + 1) * 64 + 2 * kp + 1) * 1536 + n2);
            }
        }
        // recompute S chunk
        float c[8][4];
#pragma unroll
        for (int j = 0; j < 8; j++)
#pragma unroll
            for (int q = 0; q < 4; q++) c[j][q] = 0.f;
#pragma unroll
        for (int ksh = 0; ksh < 64; ksh += 16) {
            unsigned a[4];
            ldm4(a[0], a[1], a[2], a[3], Qu + ksh * 2);
            unsigned bb[8][2];
#pragma unroll
            for (int nbp = 0; nbp < 4; nbp++)
                ldm4(bb[2 * nbp][0], bb[2 * nbp][1], bb[2 * nbp + 1][0], bb[2 * nbp + 1][1],
                     Ku + nbp * 16 * 144 + ksh * 2);
#pragma unroll
            for (int nb = 0; nb < 8; nb++) mma16(c[nb], a, bb[nb]);
        }
        // normalize + write attn (streaming)
#pragma unroll
        for (int nb = 0; nb < 8; nb++) {
            int gc = kc * 64 + nb * 8 + 2 * lq;
            float2 t0 = *(const float2*)&topo0[gc];
            float2 t1 = *(const float2*)&topo1[gc];
            c[nb][0] = __expf(c[nb][0] * scale + t0.x - m0) * inv0;
            c[nb][1] = __expf(c[nb][1] * scale + t0.y - m0) * inv0;
            c[nb][2] = __expf(c[nb][2] * scale + t1.x - m1) * inv1;
            c[nb][3] = __expf(c[nb][3] * scale + t1.y - m1) * inv1;
            __stcs((float2*)&attn_base[(size_t)r0 * 512 + gc], make_float2(c[nb][0], c[nb][1]));
            __stcs((float2*)&attn_base[(size_t)r1 * 512 + gc], make_float2(c[nb][2], c[nb][3]));
        }
        // PV: S accum fragments ARE the A fragments
#pragma unroll
        for (int kb = 0; kb < 4; kb++) {
            unsigned pa[4];
            pa[0] = pk2(c[2 * kb][0], c[2 * kb][1]);
            pa[1] = pk2(c[2 * kb][2], c[2 * kb][3]);
            pa[2] = pk2(c[2 * kb + 1][0], c[2 * kb + 1][1]);
            pa[3] = pk2(c[2 * kb + 1][2], c[2 * kb + 1][3]);
            int kw = kb * 8;
#pragma unroll
            for (int nb = 0; nb < 8; nb++) {
                int n = nb * 8 + gr;
                unsigned bb[2];
                bb[0] = Vs[(kw + lq) * 72 + n];
                bb[1] = Vs[(kw + lq + 4) * 72 + n];
                mma16(z[nb], pa, bb);
            }
        }
        if (kc < 7) {
            unsigned* Kn = Kb[(kc + 1) & 1];
            unsigned* Vn = Vb[(kc + 1) & 1];
#pragma unroll
            for (int q = 0; q < 4; q++) {
                int i = tid + q * 256;
                int r = i >> 4, c4 = (i & 15) * 4;
                *(uint2*)&Kn[r * 36 + c4 / 2] = kf[q];
            }
#pragma unroll
            for (int q = 0; q < 4; q++) {
                int i = tid + q * 256;
                int kp = i >> 5, n2 = (i & 31) * 2;
                Vn[kp * 72 + n2] = __byte_perm(vu0[q], vu1[q], 0x5410);
                Vn[kp * 72 + n2 + 1] = __byte_perm(vu0[q], vu1[q], 0x7632);
            }
        }
        __syncthreads();
    }
    int orow = b * 512 + q0 + r0;
#pragma unroll
    for (int nb = 0; nb < 8; nb++) {
        int col = h * 64 + nb * 8 + 2 * lq;
        ztb[(size_t)orow * 256 + (col >> 1)] = pk2(z[nb][0], z[nb][1]);
        ztb[(size_t)(orow + 8) * 256 + (col >> 1)] = pk2(z[nb][2], z[nb][3]);
    }
}

// ---------------------------------------------------------------------------
extern "C" void kernel_launch(void* const* d_in, const int* in_sizes, int n_in,
                              void* d_out, int out_size) {
    const float* x       = (const float*)d_in[0];
    const float* x_vel   = (const float*)d_in[1];
    const float* topo    = (const float*)d_in[2];
    const float* W_qkv   = (const float*)d_in[3];
    const float* W_vproj = (const float*)d_in[4];
    const float* W_proj  = (const float*)d_in[5];
    const float* b_proj  = (const float*)d_in[6];

    float* out    = (float*)d_out;
    float* z_man  = out;                                   // 32*512*513
    float* attn   = out + (size_t)BB * JJ * (EE + 1);      // 32*8*512*512
    float* x_tan  = attn + (size_t)BB * HH * JJ * JJ;      // 32*512*512

    void *pq, *pxt, *pvel, *pzt, *pw, *pz2, *pst;
    cudaGetSymbolAddress(&pq, g_qkv_bf);
    cudaGetSymbolAddress(&pxt, g_xt_bf);
    cudaGetSymbolAddress(&pvel, g_vel_bf);
    cudaGetSymbolAddress(&pzt, g_zt_bf);
    cudaGetSymbolAddress(&pw, g_w_bf);
    cudaGetSymbolAddress(&pz2, g_ztan2);
    cudaGetSymbolAddress(&pst, g_stats);
    unsigned* qkvb = (unsigned*)pq;
    unsigned* xtb  = (unsigned*)pxt;
    unsigned* velb = (unsigned*)pvel;
    unsigned* ztb  = (unsigned*)pzt;
    unsigned* wqkvb   = (unsigned*)pw;
    unsigned* wvprojb = wqkvb + 393216;
    unsigned* wprojb  = wvprojb + 131072;
    float* ztan2 = (float*)pz2;
    float2* stats = (float2*)pst;

    const int gemm_smem = 61440;
    const int stats_smem = 27648;
    const int main_smem = 55296;
    static int attr_set = 0;
    if (!attr_set) {
        cudaFuncSetAttribute(gemm_bf, cudaFuncAttributeMaxDynamicSharedMemorySize, gemm_smem);
        cudaFuncSetAttribute(attn_stats, cudaFuncAttributeMaxDynamicSharedMemorySize, stats_smem);
        cudaFuncSetAttribute(attn_main, cudaFuncAttributeMaxDynamicSharedMemorySize, main_smem);
        attr_set = 1;
    }

    // 0. weight conversion (merged)
    f2bf_all<<<2560, 256>>>(W_qkv, W_vproj, W_proj, wqkvb);
    // 1. log-map + vel staging
    xtan_vel_kernel<<<MROWS, 128>>>(x, x_vel, x_tan, xtb, velb);

    const __nv_bfloat16* xth = (const __nv_bfloat16*)xtb;
    const __nv_bfloat16* velh = (const __nv_bfloat16*)velb;
    const __nv_bfloat16* wqkvh = (const __nv_bfloat16*)wqkvb;
    const __nv_bfloat16* wvprojh = (const __nv_bfloat16*)wvprojb;
    const __nv_bfloat16* wprojh = (const __nv_bfloat16*)wprojb;
    const __nv_bfloat16* zth = (const __nv_bfloat16*)ztb;

    // 2. q|v slabs (N=1024 remapped), K=512
    {
        dim3 g(8, MROWS / 128);
        gemm_bf<<<g, 256, gemm_smem>>>(xth, xth, wqkvh, wqkvh, 512, 1,
                                       qkvb, 768, nullptr, 0, nullptr);
    }
    // 3. k slab: concat-K (x_tan|v_tan @ Wk|Wvproj), K=1024
    {
        dim3 g(4, MROWS / 128);
        gemm_bf<<<g, 256, gemm_smem>>>(xth, velh, wqkvh + 512 * 512, wvprojh, 1024, 0,
                                       qkvb + 256, 768, nullptr, 0, nullptr);
    }
    // 4. softmax stats
    {
        dim3 g(8, BB * HH);
        attn_stats<<<g, 128, stats_smem>>>(qkvb, topo, stats);
    }
    // 5. attn + PV
    {
        dim3 g(4, BB * HH);
        attn_main<<<g, 256, main_smem>>>(qkvb, topo, stats, attn, ztb);
    }
    // 6. out-proj
    {
        dim3 g(4, MROWS / 128);
        gemm_bf<<<g, 256, gemm_smem>>>(zth, zth, wprojh, wprojh, 512, 0,
                                       nullptr, 0, ztan2, 512, b_proj);
    }
    // 7. exp-map
    expmap_kernel<<<MROWS, 128>>>(ztan2, z_man);
}

// round 10
// speedup vs baseline: 3.4068x; 1.0820x over previous
#include <cuda_runtime.h>
#include <cuda_bf16.h>
#include <math.h>

// Problem constants
#define BB 32
#define JJ 512
#define EE 512
#define HH 8
#define MROWS (BB*JJ)          // 16384
#define EPSF 1e-7f

// Scratch (device globals; no allocation allowed). bf16 packed in unsigned.
__device__ unsigned g_qkv_bf[MROWS * 768];    // [16384,1536] bf16  q|k|v
__device__ unsigned g_xt_bf[MROWS * 256];     // x_tan bf16
__device__ unsigned g_vel_bf[MROWS * 256];    // v_tan bf16
__device__ unsigned g_zt_bf[MROWS * 256];     // attn@V bf16 (B,J,E)
__device__ unsigned g_w_bf[655360];           // wqkv | wvproj | wproj words
__device__ float    g_ztan2[MROWS * EE];      // out-proj result fp32
__device__ float2   g_stats[BB * HH * JJ];    // per attn row: (max, 1/sum)

// ---------------------------------------------------------------------------
// helpers
// ---------------------------------------------------------------------------
__device__ __forceinline__ unsigned pk2(float lo, float hi) {
    __nv_bfloat162 t = __floats2bfloat162_rn(lo, hi);
    return *reinterpret_cast<unsigned*>(&t);
}

__device__ __forceinline__ void mma16(float (&c)[4], const unsigned (&a)[4],
                                      const unsigned (&b)[2]) {
    asm volatile(
        "mma.sync.aligned.m16n8k16.row.col.f32.bf16.bf16.f32 "
        "{%0,%1,%2,%3},{%4,%5,%6,%7},{%8,%9},{%0,%1,%2,%3};"
        : "+f"(c[0]), "+f"(c[1]), "+f"(c[2]), "+f"(c[3])
        : "r"(a[0]), "r"(a[1]), "r"(a[2]), "r"(a[3]), "r"(b[0]), "r"(b[1]));
}

__device__ __forceinline__ void cp16(void* smem_dst, const void* gmem_src) {
    unsigned d = (unsigned)__cvta_generic_to_shared(smem_dst);
    asm volatile("cp.async.cg.shared.global [%0], [%1], 16;" :: "r"(d), "l"(gmem_src));
}
__device__ __forceinline__ void cp_commit() { asm volatile("cp.async.commit_group;"); }
__device__ __forceinline__ void cp_wait0() { asm volatile("cp.async.wait_group 0;"); }

__device__ __forceinline__ unsigned s2u(const void* p) {
    return (unsigned)__cvta_generic_to_shared(p);
}
__device__ __forceinline__ void ldm4(unsigned& r0, unsigned& r1, unsigned& r2,
                                     unsigned& r3, unsigned a) {
    asm volatile("ldmatrix.sync.aligned.m8n8.x4.shared.b16 {%0,%1,%2,%3}, [%4];"
                 : "=r"(r0), "=r"(r1), "=r"(r2), "=r"(r3) : "r"(a));
}

// lane offsets for ldmatrix fragments. PITCH = smem row pitch in BYTES.
// A x4: reg0 rows 0-7/k0-7, reg1 rows 8-15/k0-7, reg2 rows 0-7/k8-15, reg3 rows 8-15/k8-15
// B x4 (pair of n8 frags): reg0 n0-7/k0-7(b0), reg1 n0-7/k8-15(b1), reg2 n8-15 b0, reg3 n8-15 b1
__device__ __forceinline__ unsigned laneA_off(int lane, int pitch) {
    int sel = lane >> 3;
    return (unsigned)((((sel & 1) * 8) + (lane & 7)) * pitch + (sel >> 1) * 16);
}
__device__ __forceinline__ unsigned laneB_off(int lane, int pitch) {
    int sel = lane >> 3;
    return (unsigned)((((sel >> 1) * 8) + (lane & 7)) * pitch + (sel & 1) * 16);
}

// ---------------------------------------------------------------------------
// merged f32 -> packed bf16 weight convert
// ---------------------------------------------------------------------------
__global__ void f2bf_all(const float* __restrict__ wqkv, const float* __restrict__ wvp,
                         const float* __restrict__ wpr, unsigned* __restrict__ out) {
    int i = blockIdx.x * 256 + threadIdx.x;   // 0..655359
    const float* src;
    int j;
    if (i < 393216) { src = wqkv; j = i; }
    else if (i < 524288) { src = wvp; j = i - 393216; }
    else { src = wpr; j = i - 524288; }
    float2 f = ((const float2*)src)[j];
    out[i] = pk2(f.x, f.y);
}

// ---------------------------------------------------------------------------
// log_map0_spatial (fp32 + bf16 out) fused with vel bf16 staging
// ---------------------------------------------------------------------------
__global__ void xtan_vel_kernel(const float* __restrict__ x, const float* __restrict__ xv,
                                float* __restrict__ xt, unsigned* __restrict__ xtb,
                                unsigned* __restrict__ velb) {
    int row = blockIdx.x;
    const float* p = x + (size_t)row * 513;
    const float* pv = xv + (size_t)row * 513 + 1;
    float* o = xt + (size_t)row * 512;
    __nv_bfloat16* ob = (__nv_bfloat16*)(xtb + (size_t)row * 256);
    __nv_bfloat16* vb = (__nv_bfloat16*)(velb + (size_t)row * 256);
    int t = threadIdx.x;  // 128
    float v[4];
    float s = 0.f;
#pragma unroll
    for (int q = 0; q < 4; q++) { v[q] = p[1 + t + q * 128]; s += v[q] * v[q]; }
#pragma unroll
    for (int o2 = 16; o2 > 0; o2 >>= 1) s += __shfl_xor_sync(0xffffffffu, s, o2);
    __shared__ float sb[4];
    if ((t & 31) == 0) sb[t >> 5] = s;
    __syncthreads();
    float tot = sb[0] + sb[1] + sb[2] + sb[3];
    float nrm = sqrtf(tot);
    float x0 = fmaxf(p[0], 1.0f + 1e-7f);
    float theta = acoshf(x0);
    float sc = theta / fmaxf(nrm, EPSF);
#pragma unroll
    for (int q = 0; q < 4; q++) {
        float val = sc * v[q];
        o[t + q * 128] = val;
        ob[t + q * 128] = __float2bfloat16(val);
        vb[t + q * 128] = __float2bfloat16(pv[t + q * 128]);
    }
}

// ---------------------------------------------------------------------------
// exp_map0
// ---------------------------------------------------------------------------
__global__ void expmap_kernel(const float* __restrict__ zt, float* __restrict__ zm) {
    int row = blockIdx.x;
    const float* p = zt + (size_t)row * 512;
    float* o = zm + (size_t)row * 513;
    int t = threadIdx.x;
    float v[4];
    float s = 0.f;
#pragma unroll
    for (int q = 0; q < 4; q++) { v[q] = p[t + q * 128]; s += v[q] * v[q]; }
#pragma unroll
    for (int o2 = 16; o2 > 0; o2 >>= 1) s += __shfl_xor_sync(0xffffffffu, s, o2);
    __shared__ float sb[4];
    if ((t & 31) == 0) sb[t >> 5] = s;
    __syncthreads();
    float tot = sb[0] + sb[1] + sb[2] + sb[3];
    float nrm = sqrtf(tot);
    float sc = sinhf(nrm) / fmaxf(nrm, EPSF);
    if (t == 0) o[0] = coshf(nrm);
#pragma unroll
    for (int q = 0; q < 4; q++) o[1 + t + q * 128] = sc * v[q];
}

// ---------------------------------------------------------------------------
// bf16 GEMM, cp.async 2-stage BK=64 + ldmatrix: C[M,N] = A[M,K]*W[N,K]^T (+bias)
// Smem rows: 64 halves data, pitch 72 halves (144 B) -> conflict-free ldmatrix.
// Stage = A[128x72] + B[128x72] halves = 36864 B; 2 stages = 73728 B.
// 8 barriers for K=512 (vs 16 at BK=32); each cp.async stage covered by a
// full 64-MMA-per-warp compute block.
// ---------------------------------------------------------------------------
__global__ void __launch_bounds__(256) gemm_bf(
    const __nv_bfloat16* __restrict__ A1, const __nv_bfloat16* __restrict__ A2,
    const __nv_bfloat16* __restrict__ W1, const __nv_bfloat16* __restrict__ W2,
    int K, int remap,
    unsigned* __restrict__ Cb, int ldcw,
    float* __restrict__ Cf, int ldc, const float* __restrict__ bias) {
    extern __shared__ unsigned gsm[];   // stage s: A at s*9216 words, B at +4608
    int tid = threadIdx.x, lane = tid & 31, w = tid >> 5;
    int gr = lane >> 2, lq = lane & 3;
    int m0w = (w >> 2) * 64, n0w = (w & 3) * 32;
    unsigned lA = laneA_off(lane, 144), lB = laneB_off(lane, 144);
    int arow = blockIdx.y * 128;
    int ncol = blockIdx.x * 128;
    int wrow = (remap && ncol >= 512) ? ncol + 512 : ncol;
    const __nv_bfloat16* A1b = A1 + (size_t)arow * 512;
    const __nv_bfloat16* A2b = A2 + (size_t)arow * 512;
    const __nv_bfloat16* W1b = W1 + (size_t)wrow * 512;
    const __nv_bfloat16* W2b = W2 + (size_t)ncol * 512;
    // per-thread cp.async coords: chunk id = tid + q*256; row = id>>3, seg = (id&7)*8 halves
    int lr0 = tid >> 3, lcs = (tid & 7) * 8;

    float c[4][4][4];
#pragma unroll
    for (int i = 0; i < 4; i++)
#pragma unroll
        for (int j = 0; j < 4; j++)
#pragma unroll
            for (int q = 0; q < 4; q++) c[i][j][q] = 0.f;

    int nsteps = K / 64;
    // preload stage 0
    {
        const __nv_bfloat16* As = A1b;
        const __nv_bfloat16* Ws = W1b;
        __nv_bfloat16* sA = (__nv_bfloat16*)gsm;
        __nv_bfloat16* sB = (__nv_bfloat16*)(gsm + 4608);
#pragma unroll
        for (int q = 0; q < 4; q++) {
            int r = lr0 + q * 32;
            cp16(sA + r * 72 + lcs, As + (size_t)r * 512 + lcs);
            cp16(sB + r * 72 + lcs, Ws + (size_t)r * 512 + lcs);
        }
        cp_commit();
    }

    for (int kstep = 0; kstep < nsteps; kstep++) {
        cp_wait0();
        __syncthreads();
        if (kstep + 1 < nsteps) {
            int k0 = (kstep + 1) * 64;
            const __nv_bfloat16* As = (k0 < 512) ? A1b + k0 : A2b + (k0 - 512);
            const __nv_bfloat16* Ws = (k0 < 512) ? W1b + k0 : W2b + (k0 - 512);
            int st = (kstep + 1) & 1;
            __nv_bfloat16* sA = (__nv_bfloat16*)(gsm + st * 9216);
            __nv_bfloat16* sB = (__nv_bfloat16*)(gsm + st * 9216 + 4608);
#pragma unroll
            for (int q = 0; q < 4; q++) {
                int r = lr0 + q * 32;
                cp16(sA + r * 72 + lcs, As + (size_t)r * 512 + lcs);
                cp16(sB + r * 72 + lcs, Ws + (size_t)r * 512 + lcs);
            }
            cp_commit();
        }
        unsigned Au = s2u(gsm + (kstep & 1) * 9216);
        unsigned Bu = Au + 4608 * 4;
#pragma unroll
        for (int ksh = 0; ksh < 64; ksh += 16) {
            unsigned af[4][4], bf[4][2];
#pragma unroll
            for (int ma = 0; ma < 4; ma++)
                ldm4(af[ma][0], af[ma][1], af[ma][2], af[ma][3],
                     Au + (m0w + ma * 16) * 144 + lA + ksh * 2);
#pragma unroll
            for (int nbp = 0; nbp < 2; nbp++)
                ldm4(bf[2 * nbp][0], bf[2 * nbp][1], bf[2 * nbp + 1][0], bf[2 * nbp + 1][1],
                     Bu + (n0w + nbp * 16) * 144 + lB + ksh * 2);
#pragma unroll
            for (int ma = 0; ma < 4; ma++)
#pragma unroll
                for (int nb = 0; nb < 4; nb++) mma16(c[ma][nb], af[ma], bf[nb]);
        }
    }
    int row0 = arow + m0w;
    int col0 = wrow + n0w;
#pragma unroll
    for (int ma = 0; ma < 4; ma++)
#pragma unroll
        for (int nb = 0; nb < 4; nb++) {
            int r = row0 + ma * 16 + gr;
            int cc = col0 + nb * 8 + 2 * lq;
            if (Cb) {
                Cb[(size_t)r * ldcw + (cc >> 1)] = pk2(c[ma][nb][0], c[ma][nb][1]);
                Cb[(size_t)(r + 8) * ldcw + (cc >> 1)] = pk2(c[ma][nb][2], c[ma][nb][3]);
            } else {
                float2 v0 = make_float2(c[ma][nb][0], c[ma][nb][1]);
                float2 v1 = make_float2(c[ma][nb][2], c[ma][nb][3]);
                float bx = bias[cc], by = bias[cc + 1];
                v0.x += bx; v0.y += by; v1.x += bx; v1.y += by;
                *(float2*)&Cf[(size_t)r * ldc + cc] = v0;
                *(float2*)&Cf[(size_t)(r + 8) * ldc + cc] = v1;
            }
        }
}

// ---------------------------------------------------------------------------
// attention stats: per (64-row q-tile, head), 128 threads = 4 warps.
// Q/K tiles: 64 halves data per row, pitch 36 words (144 B) -> conflict-free.
// Dyn smem: Q[64*36w] + 2*K[64*36w] = 27648 B.
// ---------------------------------------------------------------------------
__global__ void __launch_bounds__(128) attn_stats(
    const unsigned* __restrict__ qkvb, const float* __restrict__ topo,
    float2* __restrict__ stats) {
    extern __shared__ unsigned sm[];
    unsigned* Qs = sm;                          // 64*36
    unsigned* Kb[2] = {sm + 2304, sm + 2304 + 2304};

    int q0 = blockIdx.x * 64;
    int head = blockIdx.y;
    int b = head >> 3, h = head & 7;
    int tid = threadIdx.x, lane = tid & 31, w = tid >> 5;   // w 0..3
    int lq = lane & 3;
    unsigned lA = laneA_off(lane, 144), lB = laneB_off(lane, 144);
    int gr = lane >> 2;
    int r0 = w * 16 + gr, r1 = r0 + 8;
    const __nv_bfloat16* qkvh = (const __nv_bfloat16*)qkvb;
    const __nv_bfloat16* qbase = qkvh + (size_t)b * 512 * 1536 + h * 64;
    const __nv_bfloat16* kbase = qbase + 512;
    const float scale = 0.125f;
    const float* topo0 = topo + (size_t)(q0 + r0) * 512;
    const float* topo1 = topo + (size_t)(q0 + r1) * 512;

    // load Q tile 64x64
#pragma unroll
    for (int q = 0; q < 8; q++) {
        int i = tid + q * 128;
        int r = i >> 4, c4 = (i & 15) * 4;
        *(uint2*)&Qs[r * 36 + c4 / 2] = *(const uint2*)(qbase + (size_t)(q0 + r) * 1536 + c4);
    }
    // preload K[0]
#pragma unroll
    for (int q = 0; q < 8; q++) {
        int i = tid + q * 128;
        int r = i >> 4, c4 = (i & 15) * 4;
        *(uint2*)&Kb[0][r * 36 + c4 / 2] = *(const uint2*)(kbase + (size_t)r * 1536 + c4);
    }
    __syncthreads();
    unsigned Qu = s2u(Qs) + (w * 16) * 144 + lA;

    float m0 = -1e30f, m1 = -1e30f, s0 = 0.f, s1 = 0.f;
    for (int nc = 0; nc < 8; nc++) {
        unsigned Ku = s2u(Kb[nc & 1]) + lB;
        uint2 kf[8];
        if (nc < 7) {
#pragma unroll
            for (int q = 0; q < 8; q++) {
                int i = tid + q * 128;
                int r = i >> 4, c4 = (i & 15) * 4;
                kf[q] = *(const uint2*)(kbase + (size_t)((nc + 1) * 64 + r) * 1536 + c4);
            }
        }
        float c[8][4];
#pragma unroll
        for (int j = 0; j < 8; j++)
#pragma unroll
            for (int q = 0; q < 4; q++) c[j][q] = 0.f;
#pragma unroll
        for (int ksh = 0; ksh < 64; ksh += 16) {
            unsigned a[4];
            ldm4(a[0], a[1], a[2], a[3], Qu + ksh * 2);
            unsigned bb[8][2];
#pragma unroll
            for (int nbp = 0; nbp < 4; nbp++)
                ldm4(bb[2 * nbp][0], bb[2 * nbp][1], bb[2 * nbp + 1][0], bb[2 * nbp + 1][1],
                     Ku + nbp * 16 * 144 + ksh * 2);
#pragma unroll
            for (int nb = 0; nb < 8; nb++) mma16(c[nb], a, bb[nb]);
        }
        float tm0 = -1e30f, tm1 = -1e30f;
        float v[8][4];
#pragma unroll
        for (int nb = 0; nb < 8; nb++) {
            int gc = nc * 64 + nb * 8 + 2 * lq;
            float2 t0 = *(const float2*)&topo0[gc];
            float2 t1 = *(const float2*)&topo1[gc];
            v[nb][0] = c[nb][0] * scale + t0.x;
            v[nb][1] = c[nb][1] * scale + t0.y;
            v[nb][2] = c[nb][2] * scale + t1.x;
            v[nb][3] = c[nb][3] * scale + t1.y;
            tm0 = fmaxf(tm0, fmaxf(v[nb][0], v[nb][1]));
            tm1 = fmaxf(tm1, fmaxf(v[nb][2], v[nb][3]));
        }
        tm0 = fmaxf(tm0, __shfl_xor_sync(0xffffffffu, tm0, 1));
        tm0 = fmaxf(tm0, __shfl_xor_sync(0xffffffffu, tm0, 2));
        tm1 = fmaxf(tm1, __shfl_xor_sync(0xffffffffu, tm1, 1));
        tm1 = fmaxf(tm1, __shfl_xor_sync(0xffffffffu, tm1, 2));
        float nm0 = fmaxf(m0, tm0), nm1 = fmaxf(m1, tm1);
        float ps0 = 0.f, ps1 = 0.f;
#pragma unroll
        for (int nb = 0; nb < 8; nb++) {
            ps0 += __expf(v[nb][0] - nm0) + __expf(v[nb][1] - nm0);
            ps1 += __expf(v[nb][2] - nm1) + __expf(v[nb][3] - nm1);
        }
        ps0 += __shfl_xor_sync(0xffffffffu, ps0, 1);
        ps0 += __shfl_xor_sync(0xffffffffu, ps0, 2);
        ps1 += __shfl_xor_sync(0xffffffffu, ps1, 1);
        ps1 += __shfl_xor_sync(0xffffffffu, ps1, 2);
        s0 = s0 * __expf(m0 - nm0) + ps0;
        s1 = s1 * __expf(m1 - nm1) + ps1;
        m0 = nm0; m1 = nm1;
        if (nc < 7) {
            unsigned* Kn = Kb[(nc + 1) & 1];
#pragma unroll
            for (int q = 0; q < 8; q++) {
                int i = tid + q * 128;
                int r = i >> 4, c4 = (i & 15) * 4;
                *(uint2*)&Kn[r * 36 + c4 / 2] = kf[q];
            }
        }
        __syncthreads();
    }
    if (lq == 0) {
        stats[(size_t)head * 512 + q0 + r0] = make_float2(m0, 1.0f / s0);
        stats[(size_t)head * 512 + q0 + r1] = make_float2(m1, 1.0f / s1);
    }
}

// ---------------------------------------------------------------------------
// attention main: recompute S, normalize with stats, write attn (streaming),
// PV via register-fragment path. Block = (128 q-rows, head).
// Dyn smem: Q[128*36] + 2*K[64*36] + 2*V[32*72] = 55296 B
// ---------------------------------------------------------------------------
__global__ void __launch_bounds__(256) attn_main(
    const unsigned* __restrict__ qkvb, const float* __restrict__ topo,
    const float2* __restrict__ stats,
    float* __restrict__ attn, unsigned* __restrict__ ztb) {
    extern __shared__ unsigned sm[];
    unsigned* Qs = sm;                          // 128*36
    unsigned* Kb[2] = {sm + 4608, sm + 4608 + 2304};
    unsigned* Vb[2] = {sm + 9216, sm + 9216 + 2304};

    int q0 = blockIdx.x * 128;
    int head = blockIdx.y;
    int b = head >> 3, h = head & 7;
    int tid = threadIdx.x, lane = tid & 31, w = tid >> 5;
    int gr = lane >> 2, lq = lane & 3;
    unsigned lA = laneA_off(lane, 144), lB = laneB_off(lane, 144);
    int r0 = w * 16 + gr, r1 = r0 + 8;
    const __nv_bfloat16* qkvh = (const __nv_bfloat16*)qkvb;
    const __nv_bfloat16* qbase = qkvh + (size_t)b * 512 * 1536 + h * 64;
    const __nv_bfloat16* kbase = qbase + 512;
    const __nv_bfloat16* vbase = qbase + 1024;
    const float scale = 0.125f;
    const float* topo0 = topo + (size_t)(q0 + r0) * 512;
    const float* topo1 = topo + (size_t)(q0 + r1) * 512;
    float2 st0 = stats[(size_t)head * 512 + q0 + r0];
    float2 st1 = stats[(size_t)head * 512 + q0 + r1];
    float m0 = st0.x, inv0 = st0.y, m1 = st1.x, inv1 = st1.y;

    // load Q tile (128x64)
#pragma unroll
    for (int q = 0; q < 8; q++) {
        int i = tid + q * 256;
        int r = i >> 4, c4 = (i & 15) * 4;
        *(uint2*)&Qs[r * 36 + c4 / 2] = *(const uint2*)(qbase + (size_t)(q0 + r) * 1536 + c4);
    }
    // preload K[0], V[0]
#pragma unroll
    for (int q = 0; q < 4; q++) {
        int i = tid + q * 256;
        int r = i >> 4, c4 = (i & 15) * 4;
        *(uint2*)&Kb[0][r * 36 + c4 / 2] = *(const uint2*)(kbase + (size_t)r * 1536 + c4);
    }
#pragma unroll
    for (int q = 0; q < 4; q++) {
        int i = tid + q * 256;
        int kp = i >> 5, n2 = (i & 31) * 2;
        unsigned u0 = *(const unsigned*)(vbase + (size_t)(2 * kp) * 1536 + n2);
        unsigned u1 = *(const unsigned*)(vbase + (size_t)(2 * kp + 1) * 1536 + n2);
        Vb[0][kp * 72 + n2] = __byte_perm(u0, u1, 0x5410);
        Vb[0][kp * 72 + n2 + 1] = __byte_perm(u0, u1, 0x7632);
    }
    __syncthreads();
    unsigned Qu = s2u(Qs) + (w * 16) * 144 + lA;

    float z[8][4];
#pragma unroll
    for (int j = 0; j < 8; j++)
#pragma unroll
        for (int q = 0; q < 4; q++) z[j][q] = 0.f;
    float* attn_base = attn + ((size_t)head * 512 + q0) * 512;

    for (int kc = 0; kc < 8; kc++) {
        unsigned Ku = s2u(Kb[kc & 1]) + lB;
        const unsigned* Vs = Vb[kc & 1];
        uint2 kf[4];
        unsigned vu0[4], vu1[4];
        if (kc < 7) {
#pragma unroll
            for (int q = 0; q < 4; q++) {
                int i = tid + q * 256;
                int r = i >> 4, c4 = (i & 15) * 4;
                kf[q] = *(const uint2*)(kbase + (size_t)((kc + 1) * 64 + r) * 1536 + c4);
            }
#pragma unroll
            for (int q = 0; q < 4; q++) {
                int i = tid + q * 256;
                int kp = i >> 5, n2 = (i & 31) * 2;
                vu0[q] = *(const unsigned*)(vbase + (size_t)((kc + 1) * 64 + 2 * kp) * 1536 + n2);
                vu1[q] = *(const unsigned*)(vbase + (size_t)((kc + 1) * 64 + 2 * kp + 1) * 1536 + n2);
            }
        }
        // recompute S chunk
        float c[8][4];
#pragma unroll
        for (int j = 0; j < 8; j++)
#pragma unroll
            for (int q = 0; q < 4; q++) c[j][q] = 0.f;
#pragma unroll
        for (int ksh = 0; ksh < 64; ksh += 16) {
            unsigned a[4];
            ldm4(a[0], a[1], a[2], a[3], Qu + ksh * 2);
            unsigned bb[8][2];
#pragma unroll
            for (int nbp = 0; nbp < 4; nbp++)
                ldm4(bb[2 * nbp][0], bb[2 * nbp][1], bb[2 * nbp + 1][0], bb[2 * nbp + 1][1],
                     Ku + nbp * 16 * 144 + ksh * 2);
#pragma unroll
            for (int nb = 0; nb < 8; nb++) mma16(c[nb], a, bb[nb]);
        }
        // normalize + write attn (streaming)
#pragma unroll
        for (int nb = 0; nb < 8; nb++) {
            int gc = kc * 64 + nb * 8 + 2 * lq;
            float2 t0 = *(const float2*)&topo0[gc];
            float2 t1 = *(const float2*)&topo1[gc];
            c[nb][0] = __expf(c[nb][0] * scale + t0.x - m0) * inv0;
            c[nb][1] = __expf(c[nb][1] * scale + t0.y - m0) * inv0;
            c[nb][2] = __expf(c[nb][2] * scale + t1.x - m1) * inv1;
            c[nb][3] = __expf(c[nb][3] * scale + t1.y - m1) * inv1;
            __stcs((float2*)&attn_base[(size_t)r0 * 512 + gc], make_float2(c[nb][0], c[nb][1]));
            __stcs((float2*)&attn_base[(size_t)r1 * 512 + gc], make_float2(c[nb][2], c[nb][3]));
        }
        // PV: S accum fragments ARE the A fragments
#pragma unroll
        for (int kb = 0; kb < 4; kb++) {
            unsigned pa[4];
            pa[0] = pk2(c[2 * kb][0], c[2 * kb][1]);
            pa[1] = pk2(c[2 * kb][2], c[2 * kb][3]);
            pa[2] = pk2(c[2 * kb + 1][0], c[2 * kb + 1][1]);
            pa[3] = pk2(c[2 * kb + 1][2], c[2 * kb + 1][3]);
            int kw = kb * 8;
#pragma unroll
            for (int nb = 0; nb < 8; nb++) {
                int n = nb * 8 + gr;
                unsigned bb[2];
                bb[0] = Vs[(kw + lq) * 72 + n];
                bb[1] = Vs[(kw + lq + 4) * 72 + n];
                mma16(z[nb], pa, bb);
            }
        }
        if (kc < 7) {
            unsigned* Kn = Kb[(kc + 1) & 1];
            unsigned* Vn = Vb[(kc + 1) & 1];
#pragma unroll
            for (int q = 0; q < 4; q++) {
                int i = tid + q * 256;
                int r = i >> 4, c4 = (i & 15) * 4;
                *(uint2*)&Kn[r * 36 + c4 / 2] = kf[q];
            }
#pragma unroll
            for (int q = 0; q < 4; q++) {
                int i = tid + q * 256;
                int kp = i >> 5, n2 = (i & 31) * 2;
                Vn[kp * 72 + n2] = __byte_perm(vu0[q], vu1[q], 0x5410);
                Vn[kp * 72 + n2 + 1] = __byte_perm(vu0[q], vu1[q], 0x7632);
            }
        }
        __syncthreads();
    }
    int orow = b * 512 + q0 + r0;
#pragma unroll
    for (int nb = 0; nb < 8; nb++) {
        int col = h * 64 + nb * 8 + 2 * lq;
        ztb[(size_t)orow * 256 + (col >> 1)] = pk2(z[nb][0], z[nb][1]);
        ztb[(size_t)(orow + 8) * 256 + (col >> 1)] = pk2(z[nb][2], z[nb][3]);
    }
}

// ---------------------------------------------------------------------------
extern "C" void kernel_launch(void* const* d_in, const int* in_sizes, int n_in,
                              void* d_out, int out_size) {
    const float* x       = (const float*)d_in[0];
    const float* x_vel   = (const float*)d_in[1];
    const float* topo    = (const float*)d_in[2];
    const float* W_qkv   = (const float*)d_in[3];
    const float* W_vproj = (const float*)d_in[4];
    const float* W_proj  = (const float*)d_in[5];
    const float* b_proj  = (const float*)d_in[6];

    float* out    = (float*)d_out;
    float* z_man  = out;                                   // 32*512*513
    float* attn   = out + (size_t)BB * JJ * (EE + 1);      // 32*8*512*512
    float* x_tan  = attn + (size_t)BB * HH * JJ * JJ;      // 32*512*512

    void *pq, *pxt, *pvel, *pzt, *pw, *pz2, *pst;
    cudaGetSymbolAddress(&pq, g_qkv_bf);
    cudaGetSymbolAddress(&pxt, g_xt_bf);
    cudaGetSymbolAddress(&pvel, g_vel_bf);
    cudaGetSymbolAddress(&pzt, g_zt_bf);
    cudaGetSymbolAddress(&pw, g_w_bf);
    cudaGetSymbolAddress(&pz2, g_ztan2);
    cudaGetSymbolAddress(&pst, g_stats);
    unsigned* qkvb = (unsigned*)pq;
    unsigned* xtb  = (unsigned*)pxt;
    unsigned* velb = (unsigned*)pvel;
    unsigned* ztb  = (unsigned*)pzt;
    unsigned* wqkvb   = (unsigned*)pw;
    unsigned* wvprojb = wqkvb + 393216;
    unsigned* wprojb  = wvprojb + 131072;
    float* ztan2 = (float*)pz2;
    float2* stats = (float2*)pst;

    const int gemm_smem = 73728;
    const int stats_smem = 27648;
    const int main_smem = 55296;
    static int attr_set = 0;
    if (!attr_set) {
        cudaFuncSetAttribute(gemm_bf, cudaFuncAttributeMaxDynamicSharedMemorySize, gemm_smem);
        cudaFuncSetAttribute(attn_stats, cudaFuncAttributeMaxDynamicSharedMemorySize, stats_smem);
        cudaFuncSetAttribute(attn_main, cudaFuncAttributeMaxDynamicSharedMemorySize, main_smem);
        attr_set = 1;
    }

    // 0. weight conversion (merged)
    f2bf_all<<<2560, 256>>>(W_qkv, W_vproj, W_proj, wqkvb);
    // 1. log-map + vel staging
    xtan_vel_kernel<<<MROWS, 128>>>(x, x_vel, x_tan, xtb, velb);

    const __nv_bfloat16* xth = (const __nv_bfloat16*)xtb;
    const __nv_bfloat16* velh = (const __nv_bfloat16*)velb;
    const __nv_bfloat16* wqkvh = (const __nv_bfloat16*)wqkvb;
    const __nv_bfloat16* wvprojh = (const __nv_bfloat16*)wvprojb;
    const __nv_bfloat16* wprojh = (const __nv_bfloat16*)wprojb;
    const __nv_bfloat16* zth = (const __nv_bfloat16*)ztb;

    // 2. q|v slabs (N=1024 remapped), K=512
    {
        dim3 g(8, MROWS / 128);
        gemm_bf<<<g, 256, gemm_smem>>>(xth, xth, wqkvh, wqkvh, 512, 1,
                                       qkvb, 768, nullptr, 0, nullptr);
    }
    // 3. k slab: concat-K (x_tan|v_tan @ Wk|Wvproj), K=1024
    {
        dim3 g(4, MROWS / 128);
        gemm_bf<<<g, 256, gemm_smem>>>(xth, velh, wqkvh + 512 * 512, wvprojh, 1024, 0,
                                       qkvb + 256, 768, nullptr, 0, nullptr);
    }
    // 4. softmax stats
    {
        dim3 g(8, BB * HH);
        attn_stats<<<g, 128, stats_smem>>>(qkvb, topo, stats);
    }
    // 5. attn + PV
    {
        dim3 g(4, BB * HH);
        attn_main<<<g, 256, main_smem>>>(qkvb, topo, stats, attn, ztb);
    }
    // 6. out-proj
    {
        dim3 g(4, MROWS / 128);
        gemm_bf<<<g, 256, gemm_smem>>>(zth, zth, wprojh, wprojh, 512, 0,
                                       nullptr, 0, ztan2, 512, b_proj);
    }
    // 7. exp-map
    expmap_kernel<<<MROWS, 128>>>(ztan2, z_man);
}